// round 12
// baseline (speedup 1.0000x reference)
#include <cuda_runtime.h>
#include <cuda_fp16.h>
#include <cstdint>
#include <math.h>

#define BATCH 8
#define HW 64
#define C 256
#define HEADS 8
#define DHEAD 32
#define WS 8
#define NW 64
#define NWIN (BATCH * NW)      // 512
#define TOK (BATCH * HW * HW)  // 32768
#define HIDDEN 1024
#define DEPTH 2

// ======================= scratch =======================
__device__ __half g_a[(size_t)TOK * C];          // LN1 + window out
__device__ __half g_qkv[(size_t)TOK * 3 * C];    // fp16 qkv
__device__ __half g_ao[(size_t)TOK * C];         // attention out
__device__ __half g_l2[(size_t)TOK * C];         // LN2 out
__device__ __half g_f1[(size_t)TOK * HIDDEN];    // fc1+gelu out
// transposed weights [N,K] fp16
__device__ __half g_wq[(size_t)DEPTH * 768 * 256];
__device__ __half g_wp[(size_t)DEPTH * 256 * 256];
__device__ __half g_w1[(size_t)DEPTH * 1024 * 256];
__device__ __half g_w2[(size_t)DEPTH * 256 * 1024];

__device__ __forceinline__ uint32_t smem_u32(const void* p) {
    uint32_t a;
    asm("{ .reg .u64 t; cvta.to.shared.u64 t, %1; cvt.u32.u64 %0, t; }" : "=r"(a) : "l"(p));
    return a;
}
__device__ __forceinline__ void cp16(uint32_t saddr, const void* g) {
    asm volatile("cp.async.cg.shared.global [%0], [%1], 16;" :: "r"(saddr), "l"(g));
}
#define CP_COMMIT() asm volatile("cp.async.commit_group;" ::: "memory")
#define CP_WAIT(n)  asm volatile("cp.async.wait_group %0;" :: "n"(n) : "memory")

#define LDSM_X4(r0, r1, r2, r3, addr) \
    asm volatile("ldmatrix.sync.aligned.m8n8.x4.shared.b16 {%0,%1,%2,%3}, [%4];" \
                 : "=r"(r0), "=r"(r1), "=r"(r2), "=r"(r3) : "r"(addr))

#define MMA16816(c, a, b0, b1) \
    asm volatile("mma.sync.aligned.m16n8k16.row.col.f32.f16.f16.f32 " \
                 "{%0,%1,%2,%3}, {%4,%5,%6,%7}, {%8,%9}, {%0,%1,%2,%3};" \
                 : "+f"((c)[0]), "+f"((c)[1]), "+f"((c)[2]), "+f"((c)[3]) \
                 : "r"((a)[0]), "r"((a)[1]), "r"((a)[2]), "r"((a)[3]), "r"(b0), "r"(b1))

// ======================= weight transpose + fp16 convert =======================
__global__ void wconv_kernel(const float* __restrict__ in, __half* __restrict__ oh,
                             int Kd, int Nd) {
    __shared__ float t[32][33];
    int k0 = blockIdx.x * 32, n0 = blockIdx.y * 32;
    t[threadIdx.y][threadIdx.x] = in[(size_t)(k0 + threadIdx.y) * Nd + n0 + threadIdx.x];
    __syncthreads();
    float v = t[threadIdx.x][threadIdx.y];
    int k = k0 + threadIdx.x, n = n0 + threadIdx.y;
    oh[(size_t)n * Kd + k] = __float2half_rn(v);
}

// ======================= LayerNorm: warp per row =======================
__global__ void __launch_bounds__(256) ln_kernel(
    const float* __restrict__ x, const float* __restrict__ gam,
    const float* __restrict__ bet, __half* __restrict__ oh, int shift, int gather) {
    int row = blockIdx.x * 8 + (threadIdx.x >> 5);
    int lane = threadIdx.x & 31;
    int src;
    if (gather) {
        int win = row >> 6, n = row & 63;
        int bb = win >> 6, w = win & 63;
        int wh = w >> 3, ww = w & 7, th = n >> 3, tw = n & 7;
        int pr = (wh * 8 + th + shift) & 63;
        int pc = (ww * 8 + tw + shift) & 63;
        src = (bb << 12) + (pr << 6) + pc;
    } else {
        src = row;
    }
    const float* xr = x + (size_t)src * C + lane * 8;
    float4 v0 = *reinterpret_cast<const float4*>(xr);
    float4 v1 = *reinterpret_cast<const float4*>(xr + 4);
    float s1 = v0.x + v0.y + v0.z + v0.w + v1.x + v1.y + v1.z + v1.w;
    float s2 = v0.x * v0.x + v0.y * v0.y + v0.z * v0.z + v0.w * v0.w +
               v1.x * v1.x + v1.y * v1.y + v1.z * v1.z + v1.w * v1.w;
    #pragma unroll
    for (int o = 16; o; o >>= 1) {
        s1 += __shfl_xor_sync(0xFFFFFFFFu, s1, o);
        s2 += __shfl_xor_sync(0xFFFFFFFFu, s2, o);
    }
    float mu = s1 * (1.0f / C);
    float var = s2 * (1.0f / C) - mu * mu;
    float rstd = rsqrtf(var + 1e-5f);

    float4 g0 = *reinterpret_cast<const float4*>(gam + lane * 8);
    float4 g1 = *reinterpret_cast<const float4*>(gam + lane * 8 + 4);
    float4 b0 = *reinterpret_cast<const float4*>(bet + lane * 8);
    float4 b1 = *reinterpret_cast<const float4*>(bet + lane * 8 + 4);

    float o8[8] = {
        (v0.x - mu) * rstd * g0.x + b0.x, (v0.y - mu) * rstd * g0.y + b0.y,
        (v0.z - mu) * rstd * g0.z + b0.z, (v0.w - mu) * rstd * g0.w + b0.w,
        (v1.x - mu) * rstd * g1.x + b1.x, (v1.y - mu) * rstd * g1.y + b1.y,
        (v1.z - mu) * rstd * g1.z + b1.z, (v1.w - mu) * rstd * g1.w + b1.w };
    __half hh[8];
    #pragma unroll
    for (int j = 0; j < 8; ++j) hh[j] = __float2half_rn(o8[j]);
    size_t oi = (size_t)row * C + lane * 8;
    *reinterpret_cast<uint4*>(&oh[oi]) = *reinterpret_cast<uint4*>(hh);
}

// ======================= HMMA GEMM: fp16, BK=64, 8 warps 64x32 tiles ============
// modes: 0 fp32 store | 2 residual add | 3 window-reverse scatter add
//        4 gelu -> fp16 store | 5 fp16 store
#define SPAD 72
#define TILE_EL (128 * SPAD)
#define STAGE_EL (2 * TILE_EL)
#define OFF_A 0
#define OFF_B TILE_EL
#define GEMM_SMEM (2 * STAGE_EL * 2)   // 73728 bytes

__global__ void __launch_bounds__(256, 2) gemm_mma(
    const __half* __restrict__ A, const __half* __restrict__ B,
    const float* __restrict__ bias, float* __restrict__ Cout,
    __half* __restrict__ Oh, int N, int K, int mode, int shift) {
    extern __shared__ __half smem[];
    uint32_t sb = smem_u32(smem);

    int tid = threadIdx.x, lane = tid & 31, wid = tid >> 5;
    int wm = wid >> 2, wn = wid & 3;       // 2 x 4 warp grid, 64x32 warp tiles
    int m0 = blockIdx.y * 128, n0 = blockIdx.x * 128;

    float acc[4][4][4];
    #pragma unroll
    for (int i = 0; i < 4; i++)
        #pragma unroll
        for (int j = 0; j < 4; j++)
            #pragma unroll
            for (int cjj = 0; cjj < 4; cjj++) acc[i][j][cjj] = 0.f;

    int rowA = lane & 15, colA = (lane >> 4) * 8;
    int rowB = (lane & 7) + ((lane >> 4) & 1) * 8;
    int colB = ((lane >> 3) & 1) * 8;

    // loads: 128 rows x 64 halfs per tile = 1024 x 16B; 4 cp16/thread/tile
    int ldrow = tid >> 1;                // 0..127
    int ldseg = (tid & 1) * 4;           // seg of 8 halfs: ldseg..ldseg+3
    const int nch = K >> 6;

    {
        size_t ga = (size_t)(m0 + ldrow) * K;
        size_t gb = (size_t)(n0 + ldrow) * K;
        uint32_t s0 = sb + (uint32_t)(ldrow * SPAD) * 2;
        #pragma unroll
        for (int s = 0; s < 4; ++s) {
            int c8 = (ldseg + s) * 8;
            cp16(s0 + OFF_A * 2 + c8 * 2, &A[ga + c8]);
            cp16(s0 + OFF_B * 2 + c8 * 2, &B[gb + c8]);
        }
        CP_COMMIT();
    }

    for (int ch = 0; ch < nch; ++ch) {
        if (ch + 1 < nch) {
            int k0 = (ch + 1) << 6;
            uint32_t stg = (uint32_t)((ch + 1) & 1) * STAGE_EL * 2;
            size_t ga = (size_t)(m0 + ldrow) * K + k0;
            size_t gb = (size_t)(n0 + ldrow) * K + k0;
            uint32_t s0 = sb + stg + (uint32_t)(ldrow * SPAD) * 2;
            #pragma unroll
            for (int s = 0; s < 4; ++s) {
                int c8 = (ldseg + s) * 8;
                cp16(s0 + OFF_A * 2 + c8 * 2, &A[ga + c8]);
                cp16(s0 + OFF_B * 2 + c8 * 2, &B[gb + c8]);
            }
            CP_COMMIT();
            CP_WAIT(1);
        } else {
            CP_WAIT(0);
        }
        __syncthreads();

        uint32_t stg = sb + (uint32_t)(ch & 1) * STAGE_EL * 2;
        uint32_t baseA = stg + OFF_A * 2;
        uint32_t baseB = stg + OFF_B * 2;

        #pragma unroll
        for (int ks = 0; ks < 4; ++ks) {
            uint32_t af[4][4], bf[2][4];
            #pragma unroll
            for (int am = 0; am < 4; ++am) {
                uint32_t ad = baseA + 2 * ((wm * 64 + am * 16 + rowA) * SPAD + ks * 16 + colA);
                LDSM_X4(af[am][0], af[am][1], af[am][2], af[am][3], ad);
            }
            #pragma unroll
            for (int bn = 0; bn < 2; ++bn) {
                uint32_t off = 2 * ((wn * 32 + bn * 16 + rowB) * SPAD + ks * 16 + colB);
                LDSM_X4(bf[bn][0], bf[bn][1], bf[bn][2], bf[bn][3], baseB + off);
            }
            #pragma unroll
            for (int am = 0; am < 4; ++am)
                #pragma unroll
                for (int an = 0; an < 4; ++an) {
                    int bn = an >> 1, p = (an & 1) * 2;
                    MMA16816(acc[am][an], af[am], bf[bn][p], bf[bn][p + 1]);
                }
        }
        __syncthreads();
    }

    int rbase = (lane >> 2);
    int cbase = (lane & 3) * 2;
    #pragma unroll
    for (int am = 0; am < 4; ++am) {
        #pragma unroll
        for (int h = 0; h < 2; ++h) {
            int m = m0 + wm * 64 + am * 16 + rbase + h * 8;
            int dst = m;
            if (mode == 3) {
                int win = m >> 6, n = m & 63;
                int bb = win >> 6, w = win & 63;
                int wh = w >> 3, ww = w & 7, th = n >> 3, tw = n & 7;
                int pr = (wh * 8 + th + shift) & 63;
                int pc = (ww * 8 + tw + shift) & 63;
                dst = (bb << 12) + (pr << 6) + pc;
            }
            #pragma unroll
            for (int an = 0; an < 4; ++an) {
                int col = n0 + wn * 32 + an * 8 + cbase;
                float v0 = acc[am][an][h * 2 + 0] + bias[col + 0];
                float v1 = acc[am][an][h * 2 + 1] + bias[col + 1];
                size_t oi = (size_t)dst * N + col;
                if (mode == 0) {
                    *reinterpret_cast<float2*>(&Cout[(size_t)m * N + col]) = make_float2(v0, v1);
                } else if (mode == 5) {
                    *reinterpret_cast<__half2*>(&Oh[(size_t)m * N + col]) = __floats2half2_rn(v0, v1);
                } else if (mode == 4) {
                    v0 = 0.5f * v0 * (1.0f + erff(v0 * 0.70710678118654752f));
                    v1 = 0.5f * v1 * (1.0f + erff(v1 * 0.70710678118654752f));
                    *reinterpret_cast<__half2*>(&Oh[(size_t)m * N + col]) = __floats2half2_rn(v0, v1);
                } else {  // 2 or 3: residual accumulate
                    float2 old = *reinterpret_cast<float2*>(&Cout[oi]);
                    old.x += v0;
                    old.y += v1;
                    *reinterpret_cast<float2*>(&Cout[oi]) = old;
                }
            }
        }
    }
}

// ======================= attention: fp16 in, register softmax ==================
__global__ void __launch_bounds__(256) attn_kernel(
    const __half* __restrict__ qkv, const float* __restrict__ rpb,
    __half* __restrict__ oh, int shift) {
    int bid = blockIdx.x;
    int win = bid >> 3, head = bid & 7;
    int tid = threadIdx.x;

    __shared__ float q[64][36];
    __shared__ float k[64][36];
    __shared__ float v[64][36];

    const float scale = 0.17677669529663687f;
    #pragma unroll
    for (int it = 0; it < 2; ++it) {
        int e = tid + it * 256;
        int n = e >> 3, dq = e & 7;
        size_t base = (size_t)(win * 64 + n) * (3 * C) + head * DHEAD + dq * 4;
        uint2 rq = *reinterpret_cast<const uint2*>(&qkv[base]);
        uint2 rk = *reinterpret_cast<const uint2*>(&qkv[base + C]);
        uint2 rv = *reinterpret_cast<const uint2*>(&qkv[base + 2 * C]);
        float2 q0 = __half22float2(*reinterpret_cast<__half2*>(&rq.x));
        float2 q1 = __half22float2(*reinterpret_cast<__half2*>(&rq.y));
        float2 k0 = __half22float2(*reinterpret_cast<__half2*>(&rk.x));
        float2 k1 = __half22float2(*reinterpret_cast<__half2*>(&rk.y));
        float2 vv0 = __half22float2(*reinterpret_cast<__half2*>(&rv.x));
        float2 vv1 = __half22float2(*reinterpret_cast<__half2*>(&rv.y));
        *reinterpret_cast<float4*>(&q[n][dq * 4]) =
            make_float4(q0.x * scale, q0.y * scale, q1.x * scale, q1.y * scale);
        *reinterpret_cast<float4*>(&k[n][dq * 4]) = make_float4(k0.x, k0.y, k1.x, k1.y);
        *reinterpret_cast<float4*>(&v[n][dq * 4]) = make_float4(vv0.x, vv0.y, vv1.x, vv1.y);
    }
    __syncthreads();

    int n = tid >> 2;
    int sub = tid & 3;
    int mb = sub << 4;
    int th_n = n >> 3, tw_n = n & 7;
    int w = win & 63;
    int wh = w >> 3, ww = w & 7;
    int lab_n = 0;
    if (shift) {
        int r = wh * 8 + th_n, c = ww * 8 + tw_n;
        int lr = (r < 56) ? 0 : ((r < 60) ? 1 : 2);
        int lc = (c < 56) ? 0 : ((c < 60) ? 1 : 2);
        lab_n = lr * 3 + lc;
    }

    float att[16];
    #pragma unroll
    for (int mm = 0; mm < 16; ++mm) {
        int m = mb + mm;
        float dot = 0.f;
        #pragma unroll
        for (int kq = 0; kq < 8; ++kq) {
            float4 qv = *reinterpret_cast<const float4*>(&q[n][kq * 4]);
            float4 kv = *reinterpret_cast<const float4*>(&k[m][kq * 4]);
            dot += qv.x * kv.x + qv.y * kv.y + qv.z * kv.z + qv.w * kv.w;
        }
        int th_m = m >> 3, tw_m = m & 7;
        int idx = (th_n - th_m + 7) * 15 + (tw_n - tw_m + 7);
        dot += rpb[idx * HEADS + head];
        if (shift) {
            int r = wh * 8 + th_m, c = ww * 8 + tw_m;
            int lr = (r < 56) ? 0 : ((r < 60) ? 1 : 2);
            int lc = (c < 56) ? 0 : ((c < 60) ? 1 : 2);
            if (lr * 3 + lc != lab_n) dot += -100.0f;
        }
        att[mm] = dot;
    }

    float mx = att[0];
    #pragma unroll
    for (int mm = 1; mm < 16; ++mm) mx = fmaxf(mx, att[mm]);
    mx = fmaxf(mx, __shfl_xor_sync(0xFFFFFFFFu, mx, 1));
    mx = fmaxf(mx, __shfl_xor_sync(0xFFFFFFFFu, mx, 2));
    float sum = 0.f;
    #pragma unroll
    for (int mm = 0; mm < 16; ++mm) {
        att[mm] = __expf(att[mm] - mx);
        sum += att[mm];
    }
    sum += __shfl_xor_sync(0xFFFFFFFFu, sum, 1);
    sum += __shfl_xor_sync(0xFFFFFFFFu, sum, 2);
    float inv = 1.0f / sum;
    #pragma unroll
    for (int mm = 0; mm < 16; ++mm) att[mm] *= inv;

    float4 part[8];
    #pragma unroll
    for (int dq = 0; dq < 8; ++dq) part[dq] = make_float4(0.f, 0.f, 0.f, 0.f);
    #pragma unroll
    for (int mm = 0; mm < 16; ++mm) {
        float a = att[mm];
        #pragma unroll
        for (int dq = 0; dq < 8; ++dq) {
            float4 vv = *reinterpret_cast<const float4*>(&v[mb + mm][dq * 4]);
            part[dq].x += a * vv.x;
            part[dq].y += a * vv.y;
            part[dq].z += a * vv.z;
            part[dq].w += a * vv.w;
        }
    }
    #pragma unroll
    for (int dq = 0; dq < 8; ++dq) {
        #pragma unroll
        for (int o = 1; o <= 2; o <<= 1) {
            part[dq].x += __shfl_xor_sync(0xFFFFFFFFu, part[dq].x, o);
            part[dq].y += __shfl_xor_sync(0xFFFFFFFFu, part[dq].y, o);
            part[dq].z += __shfl_xor_sync(0xFFFFFFFFu, part[dq].z, o);
            part[dq].w += __shfl_xor_sync(0xFFFFFFFFu, part[dq].w, o);
        }
    }
    {
        float o8[8] = { part[sub * 2].x, part[sub * 2].y, part[sub * 2].z, part[sub * 2].w,
                        part[sub * 2 + 1].x, part[sub * 2 + 1].y, part[sub * 2 + 1].z, part[sub * 2 + 1].w };
        __half hh[8];
        #pragma unroll
        for (int j = 0; j < 8; ++j) hh[j] = __float2half_rn(o8[j]);
        size_t oi = (size_t)(win * 64 + n) * C + head * DHEAD + sub * 8;
        *reinterpret_cast<uint4*>(&oh[oi]) = *reinterpret_cast<uint4*>(hh);
    }
}

// ======================= launch =======================
extern "C" void kernel_launch(void* const* d_in, const int* in_sizes, int n_in,
                              void* d_out, int out_size) {
    const float* x      = (const float*)d_in[0];
    const float* qkv_w  = (const float*)d_in[1];
    const float* qkv_b  = (const float*)d_in[2];
    const float* proj_w = (const float*)d_in[3];
    const float* proj_b = (const float*)d_in[4];
    const float* ln1_g  = (const float*)d_in[5];
    const float* ln1_b  = (const float*)d_in[6];
    const float* ln2_g  = (const float*)d_in[7];
    const float* ln2_b  = (const float*)d_in[8];
    const float* fc1_w  = (const float*)d_in[9];
    const float* fc1_b  = (const float*)d_in[10];
    const float* fc2_w  = (const float*)d_in[11];
    const float* fc2_b  = (const float*)d_in[12];
    const float* rpb    = (const float*)d_in[13];
    float* state = (float*)d_out;

    __half *a, *qkv, *ao, *l2, *f1, *wq, *wp, *w1, *w2;
    cudaGetSymbolAddress((void**)&a, g_a);
    cudaGetSymbolAddress((void**)&qkv, g_qkv);
    cudaGetSymbolAddress((void**)&ao, g_ao);
    cudaGetSymbolAddress((void**)&l2, g_l2);
    cudaGetSymbolAddress((void**)&f1, g_f1);
    cudaGetSymbolAddress((void**)&wq, g_wq);
    cudaGetSymbolAddress((void**)&wp, g_wp);
    cudaGetSymbolAddress((void**)&w1, g_w1);
    cudaGetSymbolAddress((void**)&w2, g_w2);

    cudaFuncSetAttribute(gemm_mma, cudaFuncAttributeMaxDynamicSharedMemorySize, GEMM_SMEM);

    cudaMemcpyAsync(state, x, (size_t)TOK * C * sizeof(float), cudaMemcpyDeviceToDevice);

    dim3 tb(32, 32);
    for (int d = 0; d < DEPTH; ++d) {
        wconv_kernel<<<dim3(256 / 32, 768 / 32), tb>>>(
            qkv_w + (size_t)d * 256 * 768, wq + (size_t)d * 768 * 256, 256, 768);
        wconv_kernel<<<dim3(256 / 32, 256 / 32), tb>>>(
            proj_w + (size_t)d * 256 * 256, wp + (size_t)d * 256 * 256, 256, 256);
        wconv_kernel<<<dim3(256 / 32, 1024 / 32), tb>>>(
            fc1_w + (size_t)d * 256 * 1024, w1 + (size_t)d * 1024 * 256, 256, 1024);
        wconv_kernel<<<dim3(1024 / 32, 256 / 32), tb>>>(
            fc2_w + (size_t)d * 1024 * 256, w2 + (size_t)d * 256 * 1024, 1024, 256);
    }

    for (int i = 0; i < DEPTH; ++i) {
        int shift = (i % 2 == 0) ? 0 : (WS / 2);
        size_t wq0 = (size_t)i * 768 * 256;
        size_t wp0 = (size_t)i * 256 * 256;
        size_t w10 = (size_t)i * 1024 * 256;
        size_t w20 = (size_t)i * 256 * 1024;

        ln_kernel<<<TOK / 8, 256>>>(state, ln1_g + i * C, ln1_b + i * C, a, shift, 1);
        gemm_mma<<<dim3(768 / 128, TOK / 128), 256, GEMM_SMEM>>>(
            a, wq + wq0, qkv_b + (size_t)i * 768, nullptr, qkv, 768, 256, 5, 0);
        attn_kernel<<<NWIN * HEADS, 256>>>(qkv, rpb + (size_t)i * 225 * HEADS, ao, shift);
        gemm_mma<<<dim3(256 / 128, TOK / 128), 256, GEMM_SMEM>>>(
            ao, wp + wp0, proj_b + (size_t)i * 256, state, nullptr, 256, 256, 3, shift);
        ln_kernel<<<TOK / 8, 256>>>(state, ln2_g + i * C, ln2_b + i * C, l2, 0, 0);
        gemm_mma<<<dim3(HIDDEN / 128, TOK / 128), 256, GEMM_SMEM>>>(
            l2, w1 + w10, fc1_b + (size_t)i * HIDDEN, nullptr, f1, HIDDEN, 256, 4, 0);
        gemm_mma<<<dim3(256 / 128, TOK / 128), 256, GEMM_SMEM>>>(
            f1, w2 + w20, fc2_b + (size_t)i * 256, state, nullptr, 256, 1024, 2, 0);
    }
}

// round 13
// speedup vs baseline: 1.6301x; 1.6301x over previous
#include <cuda_runtime.h>
#include <cuda_fp16.h>
#include <cstdint>
#include <math.h>

#define BATCH 8
#define HW 64
#define C 256
#define HEADS 8
#define DHEAD 32
#define WS 8
#define NW 64
#define NWIN (BATCH * NW)      // 512
#define TOK (BATCH * HW * HW)  // 32768
#define HIDDEN 1024
#define DEPTH 2

// ======================= scratch =======================
__device__ __half g_a[(size_t)TOK * C];          // LN1 + window out
__device__ __half g_qkv[(size_t)TOK * 3 * C];    // fp16 qkv
__device__ __half g_ao[(size_t)TOK * C];         // attention out
__device__ __half g_l2[(size_t)TOK * C];         // LN2 out
__device__ __half g_f1[(size_t)TOK * HIDDEN];    // fc1+gelu out
// transposed weights [N,K] fp16
__device__ __half g_wq[(size_t)DEPTH * 768 * 256];
__device__ __half g_wp[(size_t)DEPTH * 256 * 256];
__device__ __half g_w1[(size_t)DEPTH * 1024 * 256];
__device__ __half g_w2[(size_t)DEPTH * 256 * 1024];

__device__ __forceinline__ uint32_t smem_u32(const void* p) {
    uint32_t a;
    asm("{ .reg .u64 t; cvta.to.shared.u64 t, %1; cvt.u32.u64 %0, t; }" : "=r"(a) : "l"(p));
    return a;
}
__device__ __forceinline__ void cp16(uint32_t saddr, const void* g) {
    asm volatile("cp.async.cg.shared.global [%0], [%1], 16;" :: "r"(saddr), "l"(g));
}
#define CP_COMMIT() asm volatile("cp.async.commit_group;" ::: "memory")
#define CP_WAIT(n)  asm volatile("cp.async.wait_group %0;" :: "n"(n) : "memory")

#define LDSM_X4(r0, r1, r2, r3, addr) \
    asm volatile("ldmatrix.sync.aligned.m8n8.x4.shared.b16 {%0,%1,%2,%3}, [%4];" \
                 : "=r"(r0), "=r"(r1), "=r"(r2), "=r"(r3) : "r"(addr))

#define MMA16816(c, a, b0, b1) \
    asm volatile("mma.sync.aligned.m16n8k16.row.col.f32.f16.f16.f32 " \
                 "{%0,%1,%2,%3}, {%4,%5,%6,%7}, {%8,%9}, {%0,%1,%2,%3};" \
                 : "+f"((c)[0]), "+f"((c)[1]), "+f"((c)[2]), "+f"((c)[3]) \
                 : "r"((a)[0]), "r"((a)[1]), "r"((a)[2]), "r"((a)[3]), "r"(b0), "r"(b1))

// ======================= weight transpose + fp16 convert =======================
__global__ void wconv_kernel(const float* __restrict__ in, __half* __restrict__ oh,
                             int Kd, int Nd) {
    __shared__ float t[32][33];
    int k0 = blockIdx.x * 32, n0 = blockIdx.y * 32;
    t[threadIdx.y][threadIdx.x] = in[(size_t)(k0 + threadIdx.y) * Nd + n0 + threadIdx.x];
    __syncthreads();
    float v = t[threadIdx.x][threadIdx.y];
    int k = k0 + threadIdx.x, n = n0 + threadIdx.y;
    oh[(size_t)n * Kd + k] = __float2half_rn(v);
}

// ======================= LayerNorm: warp per row =======================
__global__ void __launch_bounds__(256) ln_kernel(
    const float* __restrict__ x, const float* __restrict__ gam,
    const float* __restrict__ bet, __half* __restrict__ oh, int shift, int gather) {
    int row = blockIdx.x * 8 + (threadIdx.x >> 5);
    int lane = threadIdx.x & 31;
    int src;
    if (gather) {
        int win = row >> 6, n = row & 63;
        int bb = win >> 6, w = win & 63;
        int wh = w >> 3, ww = w & 7, th = n >> 3, tw = n & 7;
        int pr = (wh * 8 + th + shift) & 63;
        int pc = (ww * 8 + tw + shift) & 63;
        src = (bb << 12) + (pr << 6) + pc;
    } else {
        src = row;
    }
    const float* xr = x + (size_t)src * C + lane * 8;
    float4 v0 = *reinterpret_cast<const float4*>(xr);
    float4 v1 = *reinterpret_cast<const float4*>(xr + 4);
    float s1 = v0.x + v0.y + v0.z + v0.w + v1.x + v1.y + v1.z + v1.w;
    float s2 = v0.x * v0.x + v0.y * v0.y + v0.z * v0.z + v0.w * v0.w +
               v1.x * v1.x + v1.y * v1.y + v1.z * v1.z + v1.w * v1.w;
    #pragma unroll
    for (int o = 16; o; o >>= 1) {
        s1 += __shfl_xor_sync(0xFFFFFFFFu, s1, o);
        s2 += __shfl_xor_sync(0xFFFFFFFFu, s2, o);
    }
    float mu = s1 * (1.0f / C);
    float var = s2 * (1.0f / C) - mu * mu;
    float rstd = rsqrtf(var + 1e-5f);

    float4 g0 = *reinterpret_cast<const float4*>(gam + lane * 8);
    float4 g1 = *reinterpret_cast<const float4*>(gam + lane * 8 + 4);
    float4 b0 = *reinterpret_cast<const float4*>(bet + lane * 8);
    float4 b1 = *reinterpret_cast<const float4*>(bet + lane * 8 + 4);

    float o8[8] = {
        (v0.x - mu) * rstd * g0.x + b0.x, (v0.y - mu) * rstd * g0.y + b0.y,
        (v0.z - mu) * rstd * g0.z + b0.z, (v0.w - mu) * rstd * g0.w + b0.w,
        (v1.x - mu) * rstd * g1.x + b1.x, (v1.y - mu) * rstd * g1.y + b1.y,
        (v1.z - mu) * rstd * g1.z + b1.z, (v1.w - mu) * rstd * g1.w + b1.w };
    __half hh[8];
    #pragma unroll
    for (int j = 0; j < 8; ++j) hh[j] = __float2half_rn(o8[j]);
    size_t oi = (size_t)row * C + lane * 8;
    *reinterpret_cast<uint4*>(&oh[oi]) = *reinterpret_cast<uint4*>(hh);
}

// ======================= HMMA GEMM: fp16 single pass, 8 warps 64x32 tiles =======
// modes: 0 fp32 store | 2 residual add | 3 window-reverse scatter add
//        4 gelu -> fp16 store | 5 fp16 store
#define SPAD 40
#define A_EL (128 * SPAD)
#define STAGE_EL (2 * A_EL)
#define OFF_A 0
#define OFF_B A_EL
#define GEMM_SMEM (2 * STAGE_EL * 2)   // 40960 bytes

__global__ void __launch_bounds__(256, 2) gemm_mma(
    const __half* __restrict__ A, const __half* __restrict__ B,
    const float* __restrict__ bias, float* __restrict__ Cout,
    __half* __restrict__ Oh, int N, int K, int mode, int shift) {
    extern __shared__ __half smem[];
    uint32_t sb = smem_u32(smem);

    int tid = threadIdx.x, lane = tid & 31, wid = tid >> 5;
    int wm = wid >> 2, wn = wid & 3;       // 2 x 4 warp grid, 64x32 warp tiles
    int m0 = blockIdx.y * 128, n0 = blockIdx.x * 128;

    float acc[4][4][4];
    #pragma unroll
    for (int i = 0; i < 4; i++)
        #pragma unroll
        for (int j = 0; j < 4; j++)
            #pragma unroll
            for (int cjj = 0; cjj < 4; cjj++) acc[i][j][cjj] = 0.f;

    int rowA = lane & 15, colA = (lane >> 4) * 8;
    int rowB = (lane & 7) + ((lane >> 4) & 1) * 8;
    int colB = ((lane >> 3) & 1) * 8;

    int ldrow = tid >> 1;
    int ldseg = (tid & 1) * 2;
    const int nch = K >> 5;

    {
        size_t ga = (size_t)(m0 + ldrow) * K + ldseg * 8;
        size_t gb = (size_t)(n0 + ldrow) * K + ldseg * 8;
        uint32_t s0 = sb + (uint32_t)(ldrow * SPAD + ldseg * 8) * 2;
        cp16(s0 + OFF_A * 2, &A[ga]);      cp16(s0 + OFF_A * 2 + 16, &A[ga + 8]);
        cp16(s0 + OFF_B * 2, &B[gb]);      cp16(s0 + OFF_B * 2 + 16, &B[gb + 8]);
        CP_COMMIT();
    }

    for (int ch = 0; ch < nch; ++ch) {
        if (ch + 1 < nch) {
            int k0 = (ch + 1) << 5;
            uint32_t stg = (uint32_t)((ch + 1) & 1) * STAGE_EL * 2;
            size_t ga = (size_t)(m0 + ldrow) * K + k0 + ldseg * 8;
            size_t gb = (size_t)(n0 + ldrow) * K + k0 + ldseg * 8;
            uint32_t s0 = sb + stg + (uint32_t)(ldrow * SPAD + ldseg * 8) * 2;
            cp16(s0 + OFF_A * 2, &A[ga]);  cp16(s0 + OFF_A * 2 + 16, &A[ga + 8]);
            cp16(s0 + OFF_B * 2, &B[gb]);  cp16(s0 + OFF_B * 2 + 16, &B[gb + 8]);
            CP_COMMIT();
            CP_WAIT(1);
        } else {
            CP_WAIT(0);
        }
        __syncthreads();

        uint32_t stg = sb + (uint32_t)(ch & 1) * STAGE_EL * 2;
        uint32_t baseA = stg + OFF_A * 2;
        uint32_t baseB = stg + OFF_B * 2;

        #pragma unroll
        for (int ks = 0; ks < 2; ++ks) {
            uint32_t af[4][4], bf[2][4];
            #pragma unroll
            for (int am = 0; am < 4; ++am) {
                uint32_t ad = baseA + 2 * ((wm * 64 + am * 16 + rowA) * SPAD + ks * 16 + colA);
                LDSM_X4(af[am][0], af[am][1], af[am][2], af[am][3], ad);
            }
            #pragma unroll
            for (int bn = 0; bn < 2; ++bn) {
                uint32_t off = 2 * ((wn * 32 + bn * 16 + rowB) * SPAD + ks * 16 + colB);
                LDSM_X4(bf[bn][0], bf[bn][1], bf[bn][2], bf[bn][3], baseB + off);
            }
            #pragma unroll
            for (int am = 0; am < 4; ++am)
                #pragma unroll
                for (int an = 0; an < 4; ++an) {
                    int bn = an >> 1, p = (an & 1) * 2;
                    MMA16816(acc[am][an], af[am], bf[bn][p], bf[bn][p + 1]);
                }
        }
        __syncthreads();
    }

    int rbase = (lane >> 2);
    int cbase = (lane & 3) * 2;
    #pragma unroll
    for (int am = 0; am < 4; ++am) {
        #pragma unroll
        for (int h = 0; h < 2; ++h) {
            int m = m0 + wm * 64 + am * 16 + rbase + h * 8;
            int dst = m;
            if (mode == 3) {
                int win = m >> 6, n = m & 63;
                int bb = win >> 6, w = win & 63;
                int wh = w >> 3, ww = w & 7, th = n >> 3, tw = n & 7;
                int pr = (wh * 8 + th + shift) & 63;
                int pc = (ww * 8 + tw + shift) & 63;
                dst = (bb << 12) + (pr << 6) + pc;
            }
            #pragma unroll
            for (int an = 0; an < 4; ++an) {
                int col = n0 + wn * 32 + an * 8 + cbase;
                float v0 = acc[am][an][h * 2 + 0] + bias[col + 0];
                float v1 = acc[am][an][h * 2 + 1] + bias[col + 1];
                size_t oi = (size_t)dst * N + col;
                if (mode == 0) {
                    *reinterpret_cast<float2*>(&Cout[(size_t)m * N + col]) = make_float2(v0, v1);
                } else if (mode == 5) {
                    *reinterpret_cast<__half2*>(&Oh[(size_t)m * N + col]) = __floats2half2_rn(v0, v1);
                } else if (mode == 4) {
                    v0 = 0.5f * v0 * (1.0f + erff(v0 * 0.70710678118654752f));
                    v1 = 0.5f * v1 * (1.0f + erff(v1 * 0.70710678118654752f));
                    *reinterpret_cast<__half2*>(&Oh[(size_t)m * N + col]) = __floats2half2_rn(v0, v1);
                } else {  // 2 or 3: residual accumulate
                    float2 old = *reinterpret_cast<float2*>(&Cout[oi]);
                    old.x += v0;
                    old.y += v1;
                    *reinterpret_cast<float2*>(&Cout[oi]) = old;
                }
            }
        }
    }
}

// ======================= attention: fp16 in, register softmax ==================
__global__ void __launch_bounds__(256) attn_kernel(
    const __half* __restrict__ qkv, const float* __restrict__ rpb,
    __half* __restrict__ oh, int shift) {
    int bid = blockIdx.x;
    int win = bid >> 3, head = bid & 7;
    int tid = threadIdx.x;

    __shared__ float q[64][36];
    __shared__ float k[64][36];
    __shared__ float v[64][36];

    const float scale = 0.17677669529663687f;
    #pragma unroll
    for (int it = 0; it < 2; ++it) {
        int e = tid + it * 256;
        int n = e >> 3, dq = e & 7;
        size_t base = (size_t)(win * 64 + n) * (3 * C) + head * DHEAD + dq * 4;
        uint2 rq = *reinterpret_cast<const uint2*>(&qkv[base]);
        uint2 rk = *reinterpret_cast<const uint2*>(&qkv[base + C]);
        uint2 rv = *reinterpret_cast<const uint2*>(&qkv[base + 2 * C]);
        float2 q0 = __half22float2(*reinterpret_cast<__half2*>(&rq.x));
        float2 q1 = __half22float2(*reinterpret_cast<__half2*>(&rq.y));
        float2 k0 = __half22float2(*reinterpret_cast<__half2*>(&rk.x));
        float2 k1 = __half22float2(*reinterpret_cast<__half2*>(&rk.y));
        float2 vv0 = __half22float2(*reinterpret_cast<__half2*>(&rv.x));
        float2 vv1 = __half22float2(*reinterpret_cast<__half2*>(&rv.y));
        *reinterpret_cast<float4*>(&q[n][dq * 4]) =
            make_float4(q0.x * scale, q0.y * scale, q1.x * scale, q1.y * scale);
        *reinterpret_cast<float4*>(&k[n][dq * 4]) = make_float4(k0.x, k0.y, k1.x, k1.y);
        *reinterpret_cast<float4*>(&v[n][dq * 4]) = make_float4(vv0.x, vv0.y, vv1.x, vv1.y);
    }
    __syncthreads();

    int n = tid >> 2;
    int sub = tid & 3;
    int mb = sub << 4;
    int th_n = n >> 3, tw_n = n & 7;
    int w = win & 63;
    int wh = w >> 3, ww = w & 7;
    int lab_n = 0;
    if (shift) {
        int r = wh * 8 + th_n, c = ww * 8 + tw_n;
        int lr = (r < 56) ? 0 : ((r < 60) ? 1 : 2);
        int lc = (c < 56) ? 0 : ((c < 60) ? 1 : 2);
        lab_n = lr * 3 + lc;
    }

    float att[16];
    #pragma unroll
    for (int mm = 0; mm < 16; ++mm) {
        int m = mb + mm;
        float dot = 0.f;
        #pragma unroll
        for (int kq = 0; kq < 8; ++kq) {
            float4 qv = *reinterpret_cast<const float4*>(&q[n][kq * 4]);
            float4 kv = *reinterpret_cast<const float4*>(&k[m][kq * 4]);
            dot += qv.x * kv.x + qv.y * kv.y + qv.z * kv.z + qv.w * kv.w;
        }
        int th_m = m >> 3, tw_m = m & 7;
        int idx = (th_n - th_m + 7) * 15 + (tw_n - tw_m + 7);
        dot += rpb[idx * HEADS + head];
        if (shift) {
            int r = wh * 8 + th_m, c = ww * 8 + tw_m;
            int lr = (r < 56) ? 0 : ((r < 60) ? 1 : 2);
            int lc = (c < 56) ? 0 : ((c < 60) ? 1 : 2);
            if (lr * 3 + lc != lab_n) dot += -100.0f;
        }
        att[mm] = dot;
    }

    float mx = att[0];
    #pragma unroll
    for (int mm = 1; mm < 16; ++mm) mx = fmaxf(mx, att[mm]);
    mx = fmaxf(mx, __shfl_xor_sync(0xFFFFFFFFu, mx, 1));
    mx = fmaxf(mx, __shfl_xor_sync(0xFFFFFFFFu, mx, 2));
    float sum = 0.f;
    #pragma unroll
    for (int mm = 0; mm < 16; ++mm) {
        att[mm] = __expf(att[mm] - mx);
        sum += att[mm];
    }
    sum += __shfl_xor_sync(0xFFFFFFFFu, sum, 1);
    sum += __shfl_xor_sync(0xFFFFFFFFu, sum, 2);
    float inv = 1.0f / sum;
    #pragma unroll
    for (int mm = 0; mm < 16; ++mm) att[mm] *= inv;

    float4 part[8];
    #pragma unroll
    for (int dq = 0; dq < 8; ++dq) part[dq] = make_float4(0.f, 0.f, 0.f, 0.f);
    #pragma unroll
    for (int mm = 0; mm < 16; ++mm) {
        float a = att[mm];
        #pragma unroll
        for (int dq = 0; dq < 8; ++dq) {
            float4 vv = *reinterpret_cast<const float4*>(&v[mb + mm][dq * 4]);
            part[dq].x += a * vv.x;
            part[dq].y += a * vv.y;
            part[dq].z += a * vv.z;
            part[dq].w += a * vv.w;
        }
    }
    #pragma unroll
    for (int dq = 0; dq < 8; ++dq) {
        #pragma unroll
        for (int o = 1; o <= 2; o <<= 1) {
            part[dq].x += __shfl_xor_sync(0xFFFFFFFFu, part[dq].x, o);
            part[dq].y += __shfl_xor_sync(0xFFFFFFFFu, part[dq].y, o);
            part[dq].z += __shfl_xor_sync(0xFFFFFFFFu, part[dq].z, o);
            part[dq].w += __shfl_xor_sync(0xFFFFFFFFu, part[dq].w, o);
        }
    }
    {
        float o8[8] = { part[sub * 2].x, part[sub * 2].y, part[sub * 2].z, part[sub * 2].w,
                        part[sub * 2 + 1].x, part[sub * 2 + 1].y, part[sub * 2 + 1].z, part[sub * 2 + 1].w };
        __half hh[8];
        #pragma unroll
        for (int j = 0; j < 8; ++j) hh[j] = __float2half_rn(o8[j]);
        size_t oi = (size_t)(win * 64 + n) * C + head * DHEAD + sub * 8;
        *reinterpret_cast<uint4*>(&oh[oi]) = *reinterpret_cast<uint4*>(hh);
    }
}

// ======================= launch =======================
extern "C" void kernel_launch(void* const* d_in, const int* in_sizes, int n_in,
                              void* d_out, int out_size) {
    const float* x      = (const float*)d_in[0];
    const float* qkv_w  = (const float*)d_in[1];
    const float* qkv_b  = (const float*)d_in[2];
    const float* proj_w = (const float*)d_in[3];
    const float* proj_b = (const float*)d_in[4];
    const float* ln1_g  = (const float*)d_in[5];
    const float* ln1_b  = (const float*)d_in[6];
    const float* ln2_g  = (const float*)d_in[7];
    const float* ln2_b  = (const float*)d_in[8];
    const float* fc1_w  = (const float*)d_in[9];
    const float* fc1_b  = (const float*)d_in[10];
    const float* fc2_w  = (const float*)d_in[11];
    const float* fc2_b  = (const float*)d_in[12];
    const float* rpb    = (const float*)d_in[13];
    float* state = (float*)d_out;

    __half *a, *qkv, *ao, *l2, *f1, *wq, *wp, *w1, *w2;
    cudaGetSymbolAddress((void**)&a, g_a);
    cudaGetSymbolAddress((void**)&qkv, g_qkv);
    cudaGetSymbolAddress((void**)&ao, g_ao);
    cudaGetSymbolAddress((void**)&l2, g_l2);
    cudaGetSymbolAddress((void**)&f1, g_f1);
    cudaGetSymbolAddress((void**)&wq, g_wq);
    cudaGetSymbolAddress((void**)&wp, g_wp);
    cudaGetSymbolAddress((void**)&w1, g_w1);
    cudaGetSymbolAddress((void**)&w2, g_w2);

    cudaFuncSetAttribute(gemm_mma, cudaFuncAttributeMaxDynamicSharedMemorySize, GEMM_SMEM);

    cudaMemcpyAsync(state, x, (size_t)TOK * C * sizeof(float), cudaMemcpyDeviceToDevice);

    dim3 tb(32, 32);
    for (int d = 0; d < DEPTH; ++d) {
        wconv_kernel<<<dim3(256 / 32, 768 / 32), tb>>>(
            qkv_w + (size_t)d * 256 * 768, wq + (size_t)d * 768 * 256, 256, 768);
        wconv_kernel<<<dim3(256 / 32, 256 / 32), tb>>>(
            proj_w + (size_t)d * 256 * 256, wp + (size_t)d * 256 * 256, 256, 256);
        wconv_kernel<<<dim3(256 / 32, 1024 / 32), tb>>>(
            fc1_w + (size_t)d * 256 * 1024, w1 + (size_t)d * 1024 * 256, 256, 1024);
        wconv_kernel<<<dim3(1024 / 32, 256 / 32), tb>>>(
            fc2_w + (size_t)d * 1024 * 256, w2 + (size_t)d * 256 * 1024, 1024, 256);
    }

    for (int i = 0; i < DEPTH; ++i) {
        int shift = (i % 2 == 0) ? 0 : (WS / 2);
        size_t wq0 = (size_t)i * 768 * 256;
        size_t wp0 = (size_t)i * 256 * 256;
        size_t w10 = (size_t)i * 1024 * 256;
        size_t w20 = (size_t)i * 256 * 1024;

        ln_kernel<<<TOK / 8, 256>>>(state, ln1_g + i * C, ln1_b + i * C, a, shift, 1);
        gemm_mma<<<dim3(768 / 128, TOK / 128), 256, GEMM_SMEM>>>(
            a, wq + wq0, qkv_b + (size_t)i * 768, nullptr, qkv, 768, 256, 5, 0);
        attn_kernel<<<NWIN * HEADS, 256>>>(qkv, rpb + (size_t)i * 225 * HEADS, ao, shift);
        gemm_mma<<<dim3(256 / 128, TOK / 128), 256, GEMM_SMEM>>>(
            ao, wp + wp0, proj_b + (size_t)i * 256, state, nullptr, 256, 256, 3, shift);
        ln_kernel<<<TOK / 8, 256>>>(state, ln2_g + i * C, ln2_b + i * C, l2, 0, 0);
        gemm_mma<<<dim3(HIDDEN / 128, TOK / 128), 256, GEMM_SMEM>>>(
            l2, w1 + w10, fc1_b + (size_t)i * HIDDEN, nullptr, f1, HIDDEN, 256, 4, 0);
        gemm_mma<<<dim3(256 / 128, TOK / 128), 256, GEMM_SMEM>>>(
            f1, w2 + w20, fc2_b + (size_t)i * 256, state, nullptr, 256, 1024, 2, 0);
    }
}

// round 14
// speedup vs baseline: 1.6739x; 1.0269x over previous
#include <cuda_runtime.h>
#include <cuda_fp16.h>
#include <cstdint>
#include <math.h>

#define BATCH 8
#define HW 64
#define C 256
#define HEADS 8
#define DHEAD 32
#define WS 8
#define NW 64
#define NWIN (BATCH * NW)      // 512
#define TOK (BATCH * HW * HW)  // 32768
#define HIDDEN 1024
#define DEPTH 2

// ======================= scratch =======================
__device__ __half g_a[(size_t)TOK * C];          // LN1 + window out
__device__ __half g_qkv[(size_t)TOK * 3 * C];    // fp16 qkv
__device__ __half g_ao[(size_t)TOK * C];         // attention out
__device__ __half g_l2[(size_t)TOK * C];         // LN2 out
__device__ __half g_f1[(size_t)TOK * HIDDEN];    // fc1+gelu out
// transposed weights [N,K] fp16
__device__ __half g_wq[(size_t)DEPTH * 768 * 256];
__device__ __half g_wp[(size_t)DEPTH * 256 * 256];
__device__ __half g_w1[(size_t)DEPTH * 1024 * 256];
__device__ __half g_w2[(size_t)DEPTH * 256 * 1024];

__device__ __forceinline__ uint32_t smem_u32(const void* p) {
    uint32_t a;
    asm("{ .reg .u64 t; cvta.to.shared.u64 t, %1; cvt.u32.u64 %0, t; }" : "=r"(a) : "l"(p));
    return a;
}
__device__ __forceinline__ void cp16(uint32_t saddr, const void* g) {
    asm volatile("cp.async.cg.shared.global [%0], [%1], 16;" :: "r"(saddr), "l"(g));
}
#define CP_COMMIT() asm volatile("cp.async.commit_group;" ::: "memory")
#define CP_WAIT(n)  asm volatile("cp.async.wait_group %0;" :: "n"(n) : "memory")

#define LDSM_X4(r0, r1, r2, r3, addr) \
    asm volatile("ldmatrix.sync.aligned.m8n8.x4.shared.b16 {%0,%1,%2,%3}, [%4];" \
                 : "=r"(r0), "=r"(r1), "=r"(r2), "=r"(r3) : "r"(addr))

#define MMA16816(c, a, b0, b1) \
    asm volatile("mma.sync.aligned.m16n8k16.row.col.f32.f16.f16.f32 " \
                 "{%0,%1,%2,%3}, {%4,%5,%6,%7}, {%8,%9}, {%0,%1,%2,%3};" \
                 : "+f"((c)[0]), "+f"((c)[1]), "+f"((c)[2]), "+f"((c)[3]) \
                 : "r"((a)[0]), "r"((a)[1]), "r"((a)[2]), "r"((a)[3]), "r"(b0), "r"(b1))

// ======================= weight transpose + fp16 convert (both depths) =========
__global__ void wconv_kernel(const float* __restrict__ in, __half* __restrict__ oh,
                             int Kd, int Nd) {
    __shared__ float t[32][33];
    int d = blockIdx.z;
    in += (size_t)d * Kd * Nd;
    oh += (size_t)d * Kd * Nd;
    int k0 = blockIdx.x * 32, n0 = blockIdx.y * 32;
    t[threadIdx.y][threadIdx.x] = in[(size_t)(k0 + threadIdx.y) * Nd + n0 + threadIdx.x];
    __syncthreads();
    float v = t[threadIdx.x][threadIdx.y];
    int k = k0 + threadIdx.x, n = n0 + threadIdx.y;
    oh[(size_t)n * Kd + k] = __float2half_rn(v);
}

// ======================= LayerNorm: warp per row =======================
__global__ void __launch_bounds__(256) ln_kernel(
    const float* __restrict__ x, const float* __restrict__ gam,
    const float* __restrict__ bet, __half* __restrict__ oh, int shift, int gather) {
    int row = blockIdx.x * 8 + (threadIdx.x >> 5);
    int lane = threadIdx.x & 31;
    int src;
    if (gather) {
        int win = row >> 6, n = row & 63;
        int bb = win >> 6, w = win & 63;
        int wh = w >> 3, ww = w & 7, th = n >> 3, tw = n & 7;
        int pr = (wh * 8 + th + shift) & 63;
        int pc = (ww * 8 + tw + shift) & 63;
        src = (bb << 12) + (pr << 6) + pc;
    } else {
        src = row;
    }
    const float* xr = x + (size_t)src * C + lane * 8;
    float4 v0 = *reinterpret_cast<const float4*>(xr);
    float4 v1 = *reinterpret_cast<const float4*>(xr + 4);
    float s1 = v0.x + v0.y + v0.z + v0.w + v1.x + v1.y + v1.z + v1.w;
    float s2 = v0.x * v0.x + v0.y * v0.y + v0.z * v0.z + v0.w * v0.w +
               v1.x * v1.x + v1.y * v1.y + v1.z * v1.z + v1.w * v1.w;
    #pragma unroll
    for (int o = 16; o; o >>= 1) {
        s1 += __shfl_xor_sync(0xFFFFFFFFu, s1, o);
        s2 += __shfl_xor_sync(0xFFFFFFFFu, s2, o);
    }
    float mu = s1 * (1.0f / C);
    float var = s2 * (1.0f / C) - mu * mu;
    float rstd = rsqrtf(var + 1e-5f);

    float4 g0 = *reinterpret_cast<const float4*>(gam + lane * 8);
    float4 g1 = *reinterpret_cast<const float4*>(gam + lane * 8 + 4);
    float4 b0 = *reinterpret_cast<const float4*>(bet + lane * 8);
    float4 b1 = *reinterpret_cast<const float4*>(bet + lane * 8 + 4);

    float o8[8] = {
        (v0.x - mu) * rstd * g0.x + b0.x, (v0.y - mu) * rstd * g0.y + b0.y,
        (v0.z - mu) * rstd * g0.z + b0.z, (v0.w - mu) * rstd * g0.w + b0.w,
        (v1.x - mu) * rstd * g1.x + b1.x, (v1.y - mu) * rstd * g1.y + b1.y,
        (v1.z - mu) * rstd * g1.z + b1.z, (v1.w - mu) * rstd * g1.w + b1.w };
    __half hh[8];
    #pragma unroll
    for (int j = 0; j < 8; ++j) hh[j] = __float2half_rn(o8[j]);
    size_t oi = (size_t)row * C + lane * 8;
    *reinterpret_cast<uint4*>(&oh[oi]) = *reinterpret_cast<uint4*>(hh);
}

// ======================= HMMA GEMM: fp16, BK=32, 3-stage cp.async ==============
// modes: 0 fp32 store | 2 residual add (reads Rsrc) | 3 window-reverse scatter
//        add (reads Rsrc) | 4 gelu -> fp16 store | 5 fp16 store
#define SPAD 40
#define A_EL (128 * SPAD)
#define STAGE_EL (2 * A_EL)
#define OFF_A 0
#define OFF_B A_EL
#define GEMM_SMEM (3 * STAGE_EL * 2)   // 61440 bytes

__global__ void __launch_bounds__(256, 2) gemm_mma(
    const __half* __restrict__ A, const __half* __restrict__ B,
    const float* __restrict__ bias, float* __restrict__ Cout,
    __half* __restrict__ Oh, const float* __restrict__ Rsrc,
    int N, int K, int mode, int shift) {
    extern __shared__ __half smem[];
    uint32_t sb = smem_u32(smem);

    int tid = threadIdx.x, lane = tid & 31, wid = tid >> 5;
    int wm = wid >> 2, wn = wid & 3;       // 2 x 4 warp grid, 64x32 warp tiles
    int m0 = blockIdx.y * 128, n0 = blockIdx.x * 128;

    float acc[4][4][4];
    #pragma unroll
    for (int i = 0; i < 4; i++)
        #pragma unroll
        for (int j = 0; j < 4; j++)
            #pragma unroll
            for (int cjj = 0; cjj < 4; cjj++) acc[i][j][cjj] = 0.f;

    int rowA = lane & 15, colA = (lane >> 4) * 8;
    int rowB = (lane & 7) + ((lane >> 4) & 1) * 8;
    int colB = ((lane >> 3) & 1) * 8;

    int ldrow = tid >> 1;
    int ldseg = (tid & 1) * 2;
    const int nch = K >> 5;

    // prologue: chunks 0,1 into stages 0,1 (K >= 64 always)
    #pragma unroll
    for (int p = 0; p < 2; ++p) {
        int k0 = p << 5;
        size_t ga = (size_t)(m0 + ldrow) * K + k0 + ldseg * 8;
        size_t gb = (size_t)(n0 + ldrow) * K + k0 + ldseg * 8;
        uint32_t s0 = sb + (uint32_t)p * STAGE_EL * 2 + (uint32_t)(ldrow * SPAD + ldseg * 8) * 2;
        cp16(s0 + OFF_A * 2, &A[ga]);      cp16(s0 + OFF_A * 2 + 16, &A[ga + 8]);
        cp16(s0 + OFF_B * 2, &B[gb]);      cp16(s0 + OFF_B * 2 + 16, &B[gb + 8]);
        CP_COMMIT();
    }

    int st_c = 0, st_i = 2;
    for (int ch = 0; ch < nch; ++ch) {
        if (ch + 2 < nch) {
            int k0 = (ch + 2) << 5;
            size_t ga = (size_t)(m0 + ldrow) * K + k0 + ldseg * 8;
            size_t gb = (size_t)(n0 + ldrow) * K + k0 + ldseg * 8;
            uint32_t s0 = sb + (uint32_t)st_i * STAGE_EL * 2 + (uint32_t)(ldrow * SPAD + ldseg * 8) * 2;
            cp16(s0 + OFF_A * 2, &A[ga]);  cp16(s0 + OFF_A * 2 + 16, &A[ga + 8]);
            cp16(s0 + OFF_B * 2, &B[gb]);  cp16(s0 + OFF_B * 2 + 16, &B[gb + 8]);
        }
        CP_COMMIT();           // empty group when nothing issued keeps count uniform
        CP_WAIT(2);            // chunk ch's group complete
        __syncthreads();

        uint32_t stg = sb + (uint32_t)st_c * STAGE_EL * 2;
        uint32_t baseA = stg + OFF_A * 2;
        uint32_t baseB = stg + OFF_B * 2;

        #pragma unroll
        for (int ks = 0; ks < 2; ++ks) {
            uint32_t af[4][4], bf[2][4];
            #pragma unroll
            for (int am = 0; am < 4; ++am) {
                uint32_t ad = baseA + 2 * ((wm * 64 + am * 16 + rowA) * SPAD + ks * 16 + colA);
                LDSM_X4(af[am][0], af[am][1], af[am][2], af[am][3], ad);
            }
            #pragma unroll
            for (int bn = 0; bn < 2; ++bn) {
                uint32_t off = 2 * ((wn * 32 + bn * 16 + rowB) * SPAD + ks * 16 + colB);
                LDSM_X4(bf[bn][0], bf[bn][1], bf[bn][2], bf[bn][3], baseB + off);
            }
            #pragma unroll
            for (int am = 0; am < 4; ++am)
                #pragma unroll
                for (int an = 0; an < 4; ++an) {
                    int bn = an >> 1, p = (an & 1) * 2;
                    MMA16816(acc[am][an], af[am], bf[bn][p], bf[bn][p + 1]);
                }
        }
        __syncthreads();
        st_c = (st_c == 2) ? 0 : st_c + 1;
        st_i = (st_i == 2) ? 0 : st_i + 1;
    }

    int rbase = (lane >> 2);
    int cbase = (lane & 3) * 2;
    #pragma unroll
    for (int am = 0; am < 4; ++am) {
        #pragma unroll
        for (int h = 0; h < 2; ++h) {
            int m = m0 + wm * 64 + am * 16 + rbase + h * 8;
            int dst = m;
            if (mode == 3) {
                int win = m >> 6, n = m & 63;
                int bb = win >> 6, w = win & 63;
                int wh = w >> 3, ww = w & 7, th = n >> 3, tw = n & 7;
                int pr = (wh * 8 + th + shift) & 63;
                int pc = (ww * 8 + tw + shift) & 63;
                dst = (bb << 12) + (pr << 6) + pc;
            }
            #pragma unroll
            for (int an = 0; an < 4; ++an) {
                int col = n0 + wn * 32 + an * 8 + cbase;
                float v0 = acc[am][an][h * 2 + 0] + bias[col + 0];
                float v1 = acc[am][an][h * 2 + 1] + bias[col + 1];
                size_t oi = (size_t)dst * N + col;
                if (mode == 0) {
                    *reinterpret_cast<float2*>(&Cout[(size_t)m * N + col]) = make_float2(v0, v1);
                } else if (mode == 5) {
                    *reinterpret_cast<__half2*>(&Oh[(size_t)m * N + col]) = __floats2half2_rn(v0, v1);
                } else if (mode == 4) {
                    v0 = 0.5f * v0 * (1.0f + erff(v0 * 0.70710678118654752f));
                    v1 = 0.5f * v1 * (1.0f + erff(v1 * 0.70710678118654752f));
                    *reinterpret_cast<__half2*>(&Oh[(size_t)m * N + col]) = __floats2half2_rn(v0, v1);
                } else {  // 2 or 3: residual accumulate from Rsrc (each element once)
                    float2 old = *reinterpret_cast<const float2*>(&Rsrc[oi]);
                    old.x += v0;
                    old.y += v1;
                    *reinterpret_cast<float2*>(&Cout[oi]) = old;
                }
            }
        }
    }
}

// ======================= attention: fp16 in, register softmax ==================
__global__ void __launch_bounds__(256) attn_kernel(
    const __half* __restrict__ qkv, const float* __restrict__ rpb,
    __half* __restrict__ oh, int shift) {
    int bid = blockIdx.x;
    int win = bid >> 3, head = bid & 7;
    int tid = threadIdx.x;

    __shared__ float q[64][36];
    __shared__ float k[64][36];
    __shared__ float v[64][36];

    const float scale = 0.17677669529663687f;
    #pragma unroll
    for (int it = 0; it < 2; ++it) {
        int e = tid + it * 256;
        int n = e >> 3, dq = e & 7;
        size_t base = (size_t)(win * 64 + n) * (3 * C) + head * DHEAD + dq * 4;
        uint2 rq = *reinterpret_cast<const uint2*>(&qkv[base]);
        uint2 rk = *reinterpret_cast<const uint2*>(&qkv[base + C]);
        uint2 rv = *reinterpret_cast<const uint2*>(&qkv[base + 2 * C]);
        float2 q0 = __half22float2(*reinterpret_cast<__half2*>(&rq.x));
        float2 q1 = __half22float2(*reinterpret_cast<__half2*>(&rq.y));
        float2 k0 = __half22float2(*reinterpret_cast<__half2*>(&rk.x));
        float2 k1 = __half22float2(*reinterpret_cast<__half2*>(&rk.y));
        float2 vv0 = __half22float2(*reinterpret_cast<__half2*>(&rv.x));
        float2 vv1 = __half22float2(*reinterpret_cast<__half2*>(&rv.y));
        *reinterpret_cast<float4*>(&q[n][dq * 4]) =
            make_float4(q0.x * scale, q0.y * scale, q1.x * scale, q1.y * scale);
        *reinterpret_cast<float4*>(&k[n][dq * 4]) = make_float4(k0.x, k0.y, k1.x, k1.y);
        *reinterpret_cast<float4*>(&v[n][dq * 4]) = make_float4(vv0.x, vv0.y, vv1.x, vv1.y);
    }
    __syncthreads();

    int n = tid >> 2;
    int sub = tid & 3;
    int mb = sub << 4;
    int th_n = n >> 3, tw_n = n & 7;
    int w = win & 63;
    int wh = w >> 3, ww = w & 7;
    int lab_n = 0;
    if (shift) {
        int r = wh * 8 + th_n, c = ww * 8 + tw_n;
        int lr = (r < 56) ? 0 : ((r < 60) ? 1 : 2);
        int lc = (c < 56) ? 0 : ((c < 60) ? 1 : 2);
        lab_n = lr * 3 + lc;
    }

    float att[16];
    #pragma unroll
    for (int mm = 0; mm < 16; ++mm) {
        int m = mb + mm;
        float dot = 0.f;
        #pragma unroll
        for (int kq = 0; kq < 8; ++kq) {
            float4 qv = *reinterpret_cast<const float4*>(&q[n][kq * 4]);
            float4 kv = *reinterpret_cast<const float4*>(&k[m][kq * 4]);
            dot += qv.x * kv.x + qv.y * kv.y + qv.z * kv.z + qv.w * kv.w;
        }
        int th_m = m >> 3, tw_m = m & 7;
        int idx = (th_n - th_m + 7) * 15 + (tw_n - tw_m + 7);
        dot += rpb[idx * HEADS + head];
        if (shift) {
            int r = wh * 8 + th_m, c = ww * 8 + tw_m;
            int lr = (r < 56) ? 0 : ((r < 60) ? 1 : 2);
            int lc = (c < 56) ? 0 : ((c < 60) ? 1 : 2);
            if (lr * 3 + lc != lab_n) dot += -100.0f;
        }
        att[mm] = dot;
    }

    float mx = att[0];
    #pragma unroll
    for (int mm = 1; mm < 16; ++mm) mx = fmaxf(mx, att[mm]);
    mx = fmaxf(mx, __shfl_xor_sync(0xFFFFFFFFu, mx, 1));
    mx = fmaxf(mx, __shfl_xor_sync(0xFFFFFFFFu, mx, 2));
    float sum = 0.f;
    #pragma unroll
    for (int mm = 0; mm < 16; ++mm) {
        att[mm] = __expf(att[mm] - mx);
        sum += att[mm];
    }
    sum += __shfl_xor_sync(0xFFFFFFFFu, sum, 1);
    sum += __shfl_xor_sync(0xFFFFFFFFu, sum, 2);
    float inv = 1.0f / sum;
    #pragma unroll
    for (int mm = 0; mm < 16; ++mm) att[mm] *= inv;

    float4 part[8];
    #pragma unroll
    for (int dq = 0; dq < 8; ++dq) part[dq] = make_float4(0.f, 0.f, 0.f, 0.f);
    #pragma unroll
    for (int mm = 0; mm < 16; ++mm) {
        float a = att[mm];
        #pragma unroll
        for (int dq = 0; dq < 8; ++dq) {
            float4 vv = *reinterpret_cast<const float4*>(&v[mb + mm][dq * 4]);
            part[dq].x += a * vv.x;
            part[dq].y += a * vv.y;
            part[dq].z += a * vv.z;
            part[dq].w += a * vv.w;
        }
    }
    #pragma unroll
    for (int dq = 0; dq < 8; ++dq) {
        #pragma unroll
        for (int o = 1; o <= 2; o <<= 1) {
            part[dq].x += __shfl_xor_sync(0xFFFFFFFFu, part[dq].x, o);
            part[dq].y += __shfl_xor_sync(0xFFFFFFFFu, part[dq].y, o);
            part[dq].z += __shfl_xor_sync(0xFFFFFFFFu, part[dq].z, o);
            part[dq].w += __shfl_xor_sync(0xFFFFFFFFu, part[dq].w, o);
        }
    }
    {
        float o8[8] = { part[sub * 2].x, part[sub * 2].y, part[sub * 2].z, part[sub * 2].w,
                        part[sub * 2 + 1].x, part[sub * 2 + 1].y, part[sub * 2 + 1].z, part[sub * 2 + 1].w };
        __half hh[8];
        #pragma unroll
        for (int j = 0; j < 8; ++j) hh[j] = __float2half_rn(o8[j]);
        size_t oi = (size_t)(win * 64 + n) * C + head * DHEAD + sub * 8;
        *reinterpret_cast<uint4*>(&oh[oi]) = *reinterpret_cast<uint4*>(hh);
    }
}

// ======================= launch =======================
extern "C" void kernel_launch(void* const* d_in, const int* in_sizes, int n_in,
                              void* d_out, int out_size) {
    const float* x      = (const float*)d_in[0];
    const float* qkv_w  = (const float*)d_in[1];
    const float* qkv_b  = (const float*)d_in[2];
    const float* proj_w = (const float*)d_in[3];
    const float* proj_b = (const float*)d_in[4];
    const float* ln1_g  = (const float*)d_in[5];
    const float* ln1_b  = (const float*)d_in[6];
    const float* ln2_g  = (const float*)d_in[7];
    const float* ln2_b  = (const float*)d_in[8];
    const float* fc1_w  = (const float*)d_in[9];
    const float* fc1_b  = (const float*)d_in[10];
    const float* fc2_w  = (const float*)d_in[11];
    const float* fc2_b  = (const float*)d_in[12];
    const float* rpb    = (const float*)d_in[13];
    float* state = (float*)d_out;

    __half *a, *qkv, *ao, *l2, *f1, *wq, *wp, *w1, *w2;
    cudaGetSymbolAddress((void**)&a, g_a);
    cudaGetSymbolAddress((void**)&qkv, g_qkv);
    cudaGetSymbolAddress((void**)&ao, g_ao);
    cudaGetSymbolAddress((void**)&l2, g_l2);
    cudaGetSymbolAddress((void**)&f1, g_f1);
    cudaGetSymbolAddress((void**)&wq, g_wq);
    cudaGetSymbolAddress((void**)&wp, g_wp);
    cudaGetSymbolAddress((void**)&w1, g_w1);
    cudaGetSymbolAddress((void**)&w2, g_w2);

    cudaFuncSetAttribute(gemm_mma, cudaFuncAttributeMaxDynamicSharedMemorySize, GEMM_SMEM);

    // 4 wconv launches, both depths each (grid.z = DEPTH)
    dim3 tb(32, 32);
    wconv_kernel<<<dim3(256 / 32, 768 / 32, DEPTH), tb>>>(qkv_w, wq, 256, 768);
    wconv_kernel<<<dim3(256 / 32, 256 / 32, DEPTH), tb>>>(proj_w, wp, 256, 256);
    wconv_kernel<<<dim3(256 / 32, 1024 / 32, DEPTH), tb>>>(fc1_w, w1, 256, 1024);
    wconv_kernel<<<dim3(1024 / 32, 256 / 32, DEPTH), tb>>>(fc2_w, w2, 1024, 256);

    for (int i = 0; i < DEPTH; ++i) {
        int shift = (i % 2 == 0) ? 0 : (WS / 2);
        size_t wq0 = (size_t)i * 768 * 256;
        size_t wp0 = (size_t)i * 256 * 256;
        size_t w10 = (size_t)i * 1024 * 256;
        size_t w20 = (size_t)i * 256 * 1024;
        const float* resid = (i == 0) ? x : state;   // residual stream source

        // LN1 + shift + window partition (reads x on depth 0: no state memcpy)
        ln_kernel<<<TOK / 8, 256>>>(resid, ln1_g + i * C, ln1_b + i * C, a, shift, 1);
        // qkv -> fp16   (launch #5 overall: captured by ncu)
        gemm_mma<<<dim3(768 / 128, TOK / 128), 256, GEMM_SMEM>>>(
            a, wq + wq0, qkv_b + (size_t)i * 768, nullptr, qkv, nullptr, 768, 256, 5, 0);
        attn_kernel<<<NWIN * HEADS, 256>>>(qkv, rpb + (size_t)i * 225 * HEADS, ao, shift);
        // proj + window reverse + unshift + residual (reads resid, writes state)
        gemm_mma<<<dim3(256 / 128, TOK / 128), 256, GEMM_SMEM>>>(
            ao, wp + wp0, proj_b + (size_t)i * 256, state, nullptr, resid, 256, 256, 3, shift);
        ln_kernel<<<TOK / 8, 256>>>(state, ln2_g + i * C, ln2_b + i * C, l2, 0, 0);
        gemm_mma<<<dim3(HIDDEN / 128, TOK / 128), 256, GEMM_SMEM>>>(
            l2, w1 + w10, fc1_b + (size_t)i * HIDDEN, nullptr, f1, nullptr, HIDDEN, 256, 4, 0);
        gemm_mma<<<dim3(256 / 128, TOK / 128), 256, GEMM_SMEM>>>(
            f1, w2 + w20, fc2_b + (size_t)i * 256, state, nullptr, state, 256, 1024, 2, 0);
    }
}

// round 15
// speedup vs baseline: 1.7330x; 1.0353x over previous
#include <cuda_runtime.h>
#include <cuda_fp16.h>
#include <cstdint>
#include <math.h>

#define BATCH 8
#define HW 64
#define C 256
#define HEADS 8
#define DHEAD 32
#define WS 8
#define NW 64
#define NWIN (BATCH * NW)      // 512
#define TOK (BATCH * HW * HW)  // 32768
#define HIDDEN 1024
#define DEPTH 2

// ======================= scratch =======================
__device__ __half g_a[(size_t)TOK * C];          // LN1 + window out
__device__ __half g_qkv[(size_t)TOK * 3 * C];    // fp16 qkv
__device__ __half g_ao[(size_t)TOK * C];         // attention out
__device__ __half g_l2[(size_t)TOK * C];         // LN2 out
__device__ __half g_f1[(size_t)TOK * HIDDEN];    // fc1+gelu out
// transposed weights [N,K] fp16
__device__ __half g_wq[(size_t)DEPTH * 768 * 256];
__device__ __half g_wp[(size_t)DEPTH * 256 * 256];
__device__ __half g_w1[(size_t)DEPTH * 1024 * 256];
__device__ __half g_w2[(size_t)DEPTH * 256 * 1024];

__device__ __forceinline__ uint32_t smem_u32(const void* p) {
    uint32_t a;
    asm("{ .reg .u64 t; cvta.to.shared.u64 t, %1; cvt.u32.u64 %0, t; }" : "=r"(a) : "l"(p));
    return a;
}
__device__ __forceinline__ void cp16(uint32_t saddr, const void* g) {
    asm volatile("cp.async.cg.shared.global [%0], [%1], 16;" :: "r"(saddr), "l"(g));
}
#define CP_COMMIT() asm volatile("cp.async.commit_group;" ::: "memory")
#define CP_WAIT(n)  asm volatile("cp.async.wait_group %0;" :: "n"(n) : "memory")

#define LDSM_X4(r0, r1, r2, r3, addr) \
    asm volatile("ldmatrix.sync.aligned.m8n8.x4.shared.b16 {%0,%1,%2,%3}, [%4];" \
                 : "=r"(r0), "=r"(r1), "=r"(r2), "=r"(r3) : "r"(addr))

#define MMA16816(c, a, b0, b1) \
    asm volatile("mma.sync.aligned.m16n8k16.row.col.f32.f16.f16.f32 " \
                 "{%0,%1,%2,%3}, {%4,%5,%6,%7}, {%8,%9}, {%0,%1,%2,%3};" \
                 : "+f"((c)[0]), "+f"((c)[1]), "+f"((c)[2]), "+f"((c)[3]) \
                 : "r"((a)[0]), "r"((a)[1]), "r"((a)[2]), "r"((a)[3]), "r"(b0), "r"(b1))

// ======================= weight transpose + fp16 convert (both depths) =========
__global__ void wconv_kernel(const float* __restrict__ in, __half* __restrict__ oh,
                             int Kd, int Nd) {
    __shared__ float t[32][33];
    int d = blockIdx.z;
    in += (size_t)d * Kd * Nd;
    oh += (size_t)d * Kd * Nd;
    int k0 = blockIdx.x * 32, n0 = blockIdx.y * 32;
    t[threadIdx.y][threadIdx.x] = in[(size_t)(k0 + threadIdx.y) * Nd + n0 + threadIdx.x];
    __syncthreads();
    float v = t[threadIdx.x][threadIdx.y];
    int k = k0 + threadIdx.x, n = n0 + threadIdx.y;
    oh[(size_t)n * Kd + k] = __float2half_rn(v);
}

// ======================= LayerNorm: warp per row =======================
__global__ void __launch_bounds__(256) ln_kernel(
    const float* __restrict__ x, const float* __restrict__ gam,
    const float* __restrict__ bet, __half* __restrict__ oh, int shift, int gather) {
    int row = blockIdx.x * 8 + (threadIdx.x >> 5);
    int lane = threadIdx.x & 31;
    int src;
    if (gather) {
        int win = row >> 6, n = row & 63;
        int bb = win >> 6, w = win & 63;
        int wh = w >> 3, ww = w & 7, th = n >> 3, tw = n & 7;
        int pr = (wh * 8 + th + shift) & 63;
        int pc = (ww * 8 + tw + shift) & 63;
        src = (bb << 12) + (pr << 6) + pc;
    } else {
        src = row;
    }
    const float* xr = x + (size_t)src * C + lane * 8;
    float4 v0 = *reinterpret_cast<const float4*>(xr);
    float4 v1 = *reinterpret_cast<const float4*>(xr + 4);
    float s1 = v0.x + v0.y + v0.z + v0.w + v1.x + v1.y + v1.z + v1.w;
    float s2 = v0.x * v0.x + v0.y * v0.y + v0.z * v0.z + v0.w * v0.w +
               v1.x * v1.x + v1.y * v1.y + v1.z * v1.z + v1.w * v1.w;
    #pragma unroll
    for (int o = 16; o; o >>= 1) {
        s1 += __shfl_xor_sync(0xFFFFFFFFu, s1, o);
        s2 += __shfl_xor_sync(0xFFFFFFFFu, s2, o);
    }
    float mu = s1 * (1.0f / C);
    float var = s2 * (1.0f / C) - mu * mu;
    float rstd = rsqrtf(var + 1e-5f);

    float4 g0 = *reinterpret_cast<const float4*>(gam + lane * 8);
    float4 g1 = *reinterpret_cast<const float4*>(gam + lane * 8 + 4);
    float4 b0 = *reinterpret_cast<const float4*>(bet + lane * 8);
    float4 b1 = *reinterpret_cast<const float4*>(bet + lane * 8 + 4);

    float o8[8] = {
        (v0.x - mu) * rstd * g0.x + b0.x, (v0.y - mu) * rstd * g0.y + b0.y,
        (v0.z - mu) * rstd * g0.z + b0.z, (v0.w - mu) * rstd * g0.w + b0.w,
        (v1.x - mu) * rstd * g1.x + b1.x, (v1.y - mu) * rstd * g1.y + b1.y,
        (v1.z - mu) * rstd * g1.z + b1.z, (v1.w - mu) * rstd * g1.w + b1.w };
    __half hh[8];
    #pragma unroll
    for (int j = 0; j < 8; ++j) hh[j] = __float2half_rn(o8[j]);
    size_t oi = (size_t)row * C + lane * 8;
    *reinterpret_cast<uint4*>(&oh[oi]) = *reinterpret_cast<uint4*>(hh);
}

// ======================= HMMA GEMM: fp16, BK=32, 3-stage, K templated ==========
// modes: 0 fp32 store | 2 residual add (reads Rsrc) | 3 window-reverse scatter
//        add (reads Rsrc) | 4 gelu -> fp16 store | 5 fp16 store
#define SPAD 40
#define A_EL (128 * SPAD)
#define STAGE_EL (2 * A_EL)
#define OFF_A 0
#define OFF_B A_EL
#define GEMM_SMEM (3 * STAGE_EL * 2)   // 61440 bytes

template <int K>
__global__ void __launch_bounds__(256, 2) gemm_mma(
    const __half* __restrict__ A, const __half* __restrict__ B,
    const float* __restrict__ bias, float* __restrict__ Cout,
    __half* __restrict__ Oh, const float* __restrict__ Rsrc,
    int N, int mode, int shift) {
    extern __shared__ __half smem[];
    uint32_t sb = smem_u32(smem);

    int tid = threadIdx.x, lane = tid & 31, wid = tid >> 5;
    int wm = wid >> 2, wn = wid & 3;       // 2 x 4 warp grid, 64x32 warp tiles
    int m0 = blockIdx.y * 128, n0 = blockIdx.x * 128;

    float acc[4][4][4];
    #pragma unroll
    for (int i = 0; i < 4; i++)
        #pragma unroll
        for (int j = 0; j < 4; j++)
            #pragma unroll
            for (int cjj = 0; cjj < 4; cjj++) acc[i][j][cjj] = 0.f;

    int rowA = lane & 15, colA = (lane >> 4) * 8;
    int rowB = (lane & 7) + ((lane >> 4) & 1) * 8;
    int colB = ((lane >> 3) & 1) * 8;

    int ldrow = tid >> 1;
    int ldseg = (tid & 1) * 2;
    constexpr int nch = K >> 5;

    // prologue: chunks 0,1 into stages 0,1
    #pragma unroll
    for (int p = 0; p < 2; ++p) {
        int k0 = p << 5;
        size_t ga = (size_t)(m0 + ldrow) * K + k0 + ldseg * 8;
        size_t gb = (size_t)(n0 + ldrow) * K + k0 + ldseg * 8;
        uint32_t s0 = sb + (uint32_t)p * STAGE_EL * 2 + (uint32_t)(ldrow * SPAD + ldseg * 8) * 2;
        cp16(s0 + OFF_A * 2, &A[ga]);      cp16(s0 + OFF_A * 2 + 16, &A[ga + 8]);
        cp16(s0 + OFF_B * 2, &B[gb]);      cp16(s0 + OFF_B * 2 + 16, &B[gb + 8]);
        CP_COMMIT();
    }

    #pragma unroll 8
    for (int ch = 0; ch < nch; ++ch) {
        int st_c = ch % 3;
        int st_i = (ch + 2) % 3;
        if (ch + 2 < nch) {
            int k0 = (ch + 2) << 5;
            size_t ga = (size_t)(m0 + ldrow) * K + k0 + ldseg * 8;
            size_t gb = (size_t)(n0 + ldrow) * K + k0 + ldseg * 8;
            uint32_t s0 = sb + (uint32_t)st_i * STAGE_EL * 2 + (uint32_t)(ldrow * SPAD + ldseg * 8) * 2;
            cp16(s0 + OFF_A * 2, &A[ga]);  cp16(s0 + OFF_A * 2 + 16, &A[ga + 8]);
            cp16(s0 + OFF_B * 2, &B[gb]);  cp16(s0 + OFF_B * 2 + 16, &B[gb + 8]);
        }
        CP_COMMIT();           // empty group when nothing issued keeps count uniform
        CP_WAIT(2);            // chunk ch's group complete
        __syncthreads();

        uint32_t stg = sb + (uint32_t)st_c * STAGE_EL * 2;
        uint32_t baseA = stg + OFF_A * 2;
        uint32_t baseB = stg + OFF_B * 2;

        #pragma unroll
        for (int ks = 0; ks < 2; ++ks) {
            uint32_t af[4][4], bf[2][4];
            #pragma unroll
            for (int am = 0; am < 4; ++am) {
                uint32_t ad = baseA + 2 * ((wm * 64 + am * 16 + rowA) * SPAD + ks * 16 + colA);
                LDSM_X4(af[am][0], af[am][1], af[am][2], af[am][3], ad);
            }
            #pragma unroll
            for (int bn = 0; bn < 2; ++bn) {
                uint32_t off = 2 * ((wn * 32 + bn * 16 + rowB) * SPAD + ks * 16 + colB);
                LDSM_X4(bf[bn][0], bf[bn][1], bf[bn][2], bf[bn][3], baseB + off);
            }
            #pragma unroll
            for (int am = 0; am < 4; ++am)
                #pragma unroll
                for (int an = 0; an < 4; ++an) {
                    int bn = an >> 1, p = (an & 1) * 2;
                    MMA16816(acc[am][an], af[am], bf[bn][p], bf[bn][p + 1]);
                }
        }
        __syncthreads();
    }

    int rbase = (lane >> 2);
    int cbase = (lane & 3) * 2;
    #pragma unroll
    for (int am = 0; am < 4; ++am) {
        #pragma unroll
        for (int h = 0; h < 2; ++h) {
            int m = m0 + wm * 64 + am * 16 + rbase + h * 8;
            int dst = m;
            if (mode == 3) {
                int win = m >> 6, n = m & 63;
                int bb = win >> 6, w = win & 63;
                int wh = w >> 3, ww = w & 7, th = n >> 3, tw = n & 7;
                int pr = (wh * 8 + th + shift) & 63;
                int pc = (ww * 8 + tw + shift) & 63;
                dst = (bb << 12) + (pr << 6) + pc;
            }
            #pragma unroll
            for (int an = 0; an < 4; ++an) {
                int col = n0 + wn * 32 + an * 8 + cbase;
                float v0 = acc[am][an][h * 2 + 0] + bias[col + 0];
                float v1 = acc[am][an][h * 2 + 1] + bias[col + 1];
                size_t oi = (size_t)dst * N + col;
                if (mode == 0) {
                    *reinterpret_cast<float2*>(&Cout[(size_t)m * N + col]) = make_float2(v0, v1);
                } else if (mode == 5) {
                    *reinterpret_cast<__half2*>(&Oh[(size_t)m * N + col]) = __floats2half2_rn(v0, v1);
                } else if (mode == 4) {
                    v0 = 0.5f * v0 * (1.0f + erff(v0 * 0.70710678118654752f));
                    v1 = 0.5f * v1 * (1.0f + erff(v1 * 0.70710678118654752f));
                    *reinterpret_cast<__half2*>(&Oh[(size_t)m * N + col]) = __floats2half2_rn(v0, v1);
                } else {  // 2 or 3: residual accumulate from Rsrc (each element once)
                    float2 old = *reinterpret_cast<const float2*>(&Rsrc[oi]);
                    old.x += v0;
                    old.y += v1;
                    *reinterpret_cast<float2*>(&Cout[oi]) = old;
                }
            }
        }
    }
}

// ======================= attention: fp16 in, register softmax ==================
__global__ void __launch_bounds__(256) attn_kernel(
    const __half* __restrict__ qkv, const float* __restrict__ rpb,
    __half* __restrict__ oh, int shift) {
    int bid = blockIdx.x;
    int win = bid >> 3, head = bid & 7;
    int tid = threadIdx.x;

    __shared__ float q[64][36];
    __shared__ float k[64][36];
    __shared__ float v[64][36];

    const float scale = 0.17677669529663687f;
    #pragma unroll
    for (int it = 0; it < 2; ++it) {
        int e = tid + it * 256;
        int n = e >> 3, dq = e & 7;
        size_t base = (size_t)(win * 64 + n) * (3 * C) + head * DHEAD + dq * 4;
        uint2 rq = *reinterpret_cast<const uint2*>(&qkv[base]);
        uint2 rk = *reinterpret_cast<const uint2*>(&qkv[base + C]);
        uint2 rv = *reinterpret_cast<const uint2*>(&qkv[base + 2 * C]);
        float2 q0 = __half22float2(*reinterpret_cast<__half2*>(&rq.x));
        float2 q1 = __half22float2(*reinterpret_cast<__half2*>(&rq.y));
        float2 k0 = __half22float2(*reinterpret_cast<__half2*>(&rk.x));
        float2 k1 = __half22float2(*reinterpret_cast<__half2*>(&rk.y));
        float2 vv0 = __half22float2(*reinterpret_cast<__half2*>(&rv.x));
        float2 vv1 = __half22float2(*reinterpret_cast<__half2*>(&rv.y));
        *reinterpret_cast<float4*>(&q[n][dq * 4]) =
            make_float4(q0.x * scale, q0.y * scale, q1.x * scale, q1.y * scale);
        *reinterpret_cast<float4*>(&k[n][dq * 4]) = make_float4(k0.x, k0.y, k1.x, k1.y);
        *reinterpret_cast<float4*>(&v[n][dq * 4]) = make_float4(vv0.x, vv0.y, vv1.x, vv1.y);
    }
    __syncthreads();

    int n = tid >> 2;
    int sub = tid & 3;
    int mb = sub << 4;
    int th_n = n >> 3, tw_n = n & 7;
    int w = win & 63;
    int wh = w >> 3, ww = w & 7;
    int lab_n = 0;
    if (shift) {
        int r = wh * 8 + th_n, c = ww * 8 + tw_n;
        int lr = (r < 56) ? 0 : ((r < 60) ? 1 : 2);
        int lc = (c < 56) ? 0 : ((c < 60) ? 1 : 2);
        lab_n = lr * 3 + lc;
    }

    float att[16];
    #pragma unroll
    for (int mm = 0; mm < 16; ++mm) {
        int m = mb + mm;
        float dot = 0.f;
        #pragma unroll
        for (int kq = 0; kq < 8; ++kq) {
            float4 qv = *reinterpret_cast<const float4*>(&q[n][kq * 4]);
            float4 kv = *reinterpret_cast<const float4*>(&k[m][kq * 4]);
            dot += qv.x * kv.x + qv.y * kv.y + qv.z * kv.z + qv.w * kv.w;
        }
        int th_m = m >> 3, tw_m = m & 7;
        int idx = (th_n - th_m + 7) * 15 + (tw_n - tw_m + 7);
        dot += rpb[idx * HEADS + head];
        if (shift) {
            int r = wh * 8 + th_m, c = ww * 8 + tw_m;
            int lr = (r < 56) ? 0 : ((r < 60) ? 1 : 2);
            int lc = (c < 56) ? 0 : ((c < 60) ? 1 : 2);
            if (lr * 3 + lc != lab_n) dot += -100.0f;
        }
        att[mm] = dot;
    }

    float mx = att[0];
    #pragma unroll
    for (int mm = 1; mm < 16; ++mm) mx = fmaxf(mx, att[mm]);
    mx = fmaxf(mx, __shfl_xor_sync(0xFFFFFFFFu, mx, 1));
    mx = fmaxf(mx, __shfl_xor_sync(0xFFFFFFFFu, mx, 2));
    float sum = 0.f;
    #pragma unroll
    for (int mm = 0; mm < 16; ++mm) {
        att[mm] = __expf(att[mm] - mx);
        sum += att[mm];
    }
    sum += __shfl_xor_sync(0xFFFFFFFFu, sum, 1);
    sum += __shfl_xor_sync(0xFFFFFFFFu, sum, 2);
    float inv = 1.0f / sum;
    #pragma unroll
    for (int mm = 0; mm < 16; ++mm) att[mm] *= inv;

    float4 part[8];
    #pragma unroll
    for (int dq = 0; dq < 8; ++dq) part[dq] = make_float4(0.f, 0.f, 0.f, 0.f);
    #pragma unroll
    for (int mm = 0; mm < 16; ++mm) {
        float a = att[mm];
        #pragma unroll
        for (int dq = 0; dq < 8; ++dq) {
            float4 vv = *reinterpret_cast<const float4*>(&v[mb + mm][dq * 4]);
            part[dq].x += a * vv.x;
            part[dq].y += a * vv.y;
            part[dq].z += a * vv.z;
            part[dq].w += a * vv.w;
        }
    }
    #pragma unroll
    for (int dq = 0; dq < 8; ++dq) {
        #pragma unroll
        for (int o = 1; o <= 2; o <<= 1) {
            part[dq].x += __shfl_xor_sync(0xFFFFFFFFu, part[dq].x, o);
            part[dq].y += __shfl_xor_sync(0xFFFFFFFFu, part[dq].y, o);
            part[dq].z += __shfl_xor_sync(0xFFFFFFFFu, part[dq].z, o);
            part[dq].w += __shfl_xor_sync(0xFFFFFFFFu, part[dq].w, o);
        }
    }
    {
        float o8[8] = { part[sub * 2].x, part[sub * 2].y, part[sub * 2].z, part[sub * 2].w,
                        part[sub * 2 + 1].x, part[sub * 2 + 1].y, part[sub * 2 + 1].z, part[sub * 2 + 1].w };
        __half hh[8];
        #pragma unroll
        for (int j = 0; j < 8; ++j) hh[j] = __float2half_rn(o8[j]);
        size_t oi = (size_t)(win * 64 + n) * C + head * DHEAD + sub * 8;
        *reinterpret_cast<uint4*>(&oh[oi]) = *reinterpret_cast<uint4*>(hh);
    }
}

// ======================= launch =======================
extern "C" void kernel_launch(void* const* d_in, const int* in_sizes, int n_in,
                              void* d_out, int out_size) {
    const float* x      = (const float*)d_in[0];
    const float* qkv_w  = (const float*)d_in[1];
    const float* qkv_b  = (const float*)d_in[2];
    const float* proj_w = (const float*)d_in[3];
    const float* proj_b = (const float*)d_in[4];
    const float* ln1_g  = (const float*)d_in[5];
    const float* ln1_b  = (const float*)d_in[6];
    const float* ln2_g  = (const float*)d_in[7];
    const float* ln2_b  = (const float*)d_in[8];
    const float* fc1_w  = (const float*)d_in[9];
    const float* fc1_b  = (const float*)d_in[10];
    const float* fc2_w  = (const float*)d_in[11];
    const float* fc2_b  = (const float*)d_in[12];
    const float* rpb    = (const float*)d_in[13];
    float* state = (float*)d_out;

    __half *a, *qkv, *ao, *l2, *f1, *wq, *wp, *w1, *w2;
    cudaGetSymbolAddress((void**)&a, g_a);
    cudaGetSymbolAddress((void**)&qkv, g_qkv);
    cudaGetSymbolAddress((void**)&ao, g_ao);
    cudaGetSymbolAddress((void**)&l2, g_l2);
    cudaGetSymbolAddress((void**)&f1, g_f1);
    cudaGetSymbolAddress((void**)&wq, g_wq);
    cudaGetSymbolAddress((void**)&wp, g_wp);
    cudaGetSymbolAddress((void**)&w1, g_w1);
    cudaGetSymbolAddress((void**)&w2, g_w2);

    cudaFuncSetAttribute(gemm_mma<256>, cudaFuncAttributeMaxDynamicSharedMemorySize, GEMM_SMEM);
    cudaFuncSetAttribute(gemm_mma<1024>, cudaFuncAttributeMaxDynamicSharedMemorySize, GEMM_SMEM);

    dim3 tb(32, 32);
    // just-in-time wconv ordering: gemm_qkv lands at launch index 2, attn at 3
    wconv_kernel<<<dim3(256 / 32, 768 / 32, DEPTH), tb>>>(qkv_w, wq, 256, 768);       // 0

    for (int i = 0; i < DEPTH; ++i) {
        int shift = (i % 2 == 0) ? 0 : (WS / 2);
        size_t wq0 = (size_t)i * 768 * 256;
        size_t wp0 = (size_t)i * 256 * 256;
        size_t w10 = (size_t)i * 1024 * 256;
        size_t w20 = (size_t)i * 256 * 1024;
        const float* resid = (i == 0) ? x : state;   // residual stream source

        // LN1 + shift + window partition
        ln_kernel<<<TOK / 8, 256>>>(resid, ln1_g + i * C, ln1_b + i * C, a, shift, 1);    // 1
        // qkv -> fp16   (index 2 on depth 0: ncu capture target)
        gemm_mma<256><<<dim3(768 / 128, TOK / 128), 256, GEMM_SMEM>>>(
            a, wq + wq0, qkv_b + (size_t)i * 768, nullptr, qkv, nullptr, 768, 5, 0);      // 2
        attn_kernel<<<NWIN * HEADS, 256>>>(qkv, rpb + (size_t)i * 225 * HEADS, ao, shift);// 3
        if (i == 0)
            wconv_kernel<<<dim3(256 / 32, 256 / 32, DEPTH), tb>>>(proj_w, wp, 256, 256);  // 4
        // proj + window reverse + unshift + residual
        gemm_mma<256><<<dim3(256 / 128, TOK / 128), 256, GEMM_SMEM>>>(
            ao, wp + wp0, proj_b + (size_t)i * 256, state, nullptr, resid, 256, 3, shift);
        if (i == 0)
            wconv_kernel<<<dim3(256 / 32, 1024 / 32, DEPTH), tb>>>(fc1_w, w1, 256, 1024);
        ln_kernel<<<TOK / 8, 256>>>(state, ln2_g + i * C, ln2_b + i * C, l2, 0, 0);
        gemm_mma<256><<<dim3(HIDDEN / 128, TOK / 128), 256, GEMM_SMEM>>>(
            l2, w1 + w10, fc1_b + (size_t)i * HIDDEN, nullptr, f1, nullptr, HIDDEN, 4, 0);
        if (i == 0)
            wconv_kernel<<<dim3(1024 / 32, 256 / 32, DEPTH), tb>>>(fc2_w, w2, 1024, 256);
        gemm_mma<1024><<<dim3(256 / 128, TOK / 128), 256, GEMM_SMEM>>>(
            f1, w2 + w20, fc2_b + (size_t)i * 256, state, nullptr, state, 256, 2, 0);
    }
}

// round 16
// speedup vs baseline: 3.0427x; 1.7558x over previous
#include <cuda_runtime.h>
#include <cuda_fp16.h>
#include <cstdint>
#include <math.h>

#define BATCH 8
#define HW 64
#define C 256
#define HEADS 8
#define DHEAD 32
#define WS 8
#define NW 64
#define NWIN (BATCH * NW)      // 512
#define TOK (BATCH * HW * HW)  // 32768
#define HIDDEN 1024
#define DEPTH 2

// ======================= scratch =======================
__device__ __half g_a[(size_t)TOK * C];          // LN1 + window out
__device__ __half g_qkv[(size_t)TOK * 3 * C];    // fp16 qkv
__device__ __half g_ao[(size_t)TOK * C];         // attention out
__device__ __half g_l2[(size_t)TOK * C];         // LN2 out
__device__ __half g_f1[(size_t)TOK * HIDDEN];    // fc1+gelu out
// transposed weights [N,K] fp16
__device__ __half g_wq[(size_t)DEPTH * 768 * 256];
__device__ __half g_wp[(size_t)DEPTH * 256 * 256];
__device__ __half g_w1[(size_t)DEPTH * 1024 * 256];
__device__ __half g_w2[(size_t)DEPTH * 256 * 1024];

__device__ __forceinline__ uint32_t smem_u32(const void* p) {
    uint32_t a;
    asm("{ .reg .u64 t; cvta.to.shared.u64 t, %1; cvt.u32.u64 %0, t; }" : "=r"(a) : "l"(p));
    return a;
}
__device__ __forceinline__ void cp16(uint32_t saddr, const void* g) {
    asm volatile("cp.async.cg.shared.global [%0], [%1], 16;" :: "r"(saddr), "l"(g));
}
#define CP_COMMIT() asm volatile("cp.async.commit_group;" ::: "memory")
#define CP_WAIT(n)  asm volatile("cp.async.wait_group %0;" :: "n"(n) : "memory")

#define LDSM_X4(r0, r1, r2, r3, addr) \
    asm volatile("ldmatrix.sync.aligned.m8n8.x4.shared.b16 {%0,%1,%2,%3}, [%4];" \
                 : "=r"(r0), "=r"(r1), "=r"(r2), "=r"(r3) : "r"(addr))

#define MMA16816(c, a, b0, b1) \
    asm volatile("mma.sync.aligned.m16n8k16.row.col.f32.f16.f16.f32 " \
                 "{%0,%1,%2,%3}, {%4,%5,%6,%7}, {%8,%9}, {%0,%1,%2,%3};" \
                 : "+f"((c)[0]), "+f"((c)[1]), "+f"((c)[2]), "+f"((c)[3]) \
                 : "r"((a)[0]), "r"((a)[1]), "r"((a)[2]), "r"((a)[3]), "r"(b0), "r"(b1))

// ======================= weight transpose + fp16 convert (both depths) =========
__global__ void wconv_kernel(const float* __restrict__ in, __half* __restrict__ oh,
                             int Kd, int Nd) {
    __shared__ float t[32][33];
    int d = blockIdx.z;
    in += (size_t)d * Kd * Nd;
    oh += (size_t)d * Kd * Nd;
    int k0 = blockIdx.x * 32, n0 = blockIdx.y * 32;
    t[threadIdx.y][threadIdx.x] = in[(size_t)(k0 + threadIdx.y) * Nd + n0 + threadIdx.x];
    __syncthreads();
    float v = t[threadIdx.x][threadIdx.y];
    int k = k0 + threadIdx.x, n = n0 + threadIdx.y;
    oh[(size_t)n * Kd + k] = __float2half_rn(v);
}

// ======================= LayerNorm: warp per row =======================
__global__ void __launch_bounds__(256) ln_kernel(
    const float* __restrict__ x, const float* __restrict__ gam,
    const float* __restrict__ bet, __half* __restrict__ oh, int shift, int gather) {
    int row = blockIdx.x * 8 + (threadIdx.x >> 5);
    int lane = threadIdx.x & 31;
    int src;
    if (gather) {
        int win = row >> 6, n = row & 63;
        int bb = win >> 6, w = win & 63;
        int wh = w >> 3, ww = w & 7, th = n >> 3, tw = n & 7;
        int pr = (wh * 8 + th + shift) & 63;
        int pc = (ww * 8 + tw + shift) & 63;
        src = (bb << 12) + (pr << 6) + pc;
    } else {
        src = row;
    }
    const float* xr = x + (size_t)src * C + lane * 8;
    float4 v0 = *reinterpret_cast<const float4*>(xr);
    float4 v1 = *reinterpret_cast<const float4*>(xr + 4);
    float s1 = v0.x + v0.y + v0.z + v0.w + v1.x + v1.y + v1.z + v1.w;
    float s2 = v0.x * v0.x + v0.y * v0.y + v0.z * v0.z + v0.w * v0.w +
               v1.x * v1.x + v1.y * v1.y + v1.z * v1.z + v1.w * v1.w;
    #pragma unroll
    for (int o = 16; o; o >>= 1) {
        s1 += __shfl_xor_sync(0xFFFFFFFFu, s1, o);
        s2 += __shfl_xor_sync(0xFFFFFFFFu, s2, o);
    }
    float mu = s1 * (1.0f / C);
    float var = s2 * (1.0f / C) - mu * mu;
    float rstd = rsqrtf(var + 1e-5f);

    float4 g0 = *reinterpret_cast<const float4*>(gam + lane * 8);
    float4 g1 = *reinterpret_cast<const float4*>(gam + lane * 8 + 4);
    float4 b0 = *reinterpret_cast<const float4*>(bet + lane * 8);
    float4 b1 = *reinterpret_cast<const float4*>(bet + lane * 8 + 4);

    float o8[8] = {
        (v0.x - mu) * rstd * g0.x + b0.x, (v0.y - mu) * rstd * g0.y + b0.y,
        (v0.z - mu) * rstd * g0.z + b0.z, (v0.w - mu) * rstd * g0.w + b0.w,
        (v1.x - mu) * rstd * g1.x + b1.x, (v1.y - mu) * rstd * g1.y + b1.y,
        (v1.z - mu) * rstd * g1.z + b1.z, (v1.w - mu) * rstd * g1.w + b1.w };
    __half hh[8];
    #pragma unroll
    for (int j = 0; j < 8; ++j) hh[j] = __float2half_rn(o8[j]);
    size_t oi = (size_t)row * C + lane * 8;
    *reinterpret_cast<uint4*>(&oh[oi]) = *reinterpret_cast<uint4*>(hh);
}

// ======================= HMMA GEMM: fp16, BK=32, 3-stage, K templated ==========
// modes: 0 fp32 store | 2 residual add (reads Rsrc) | 3 window-reverse scatter
//        add (reads Rsrc) | 4 gelu -> fp16 store | 5 fp16 store
#define SPAD 40
#define A_EL (128 * SPAD)
#define STAGE_EL (2 * A_EL)
#define OFF_A 0
#define OFF_B A_EL
#define GEMM_SMEM (3 * STAGE_EL * 2)   // 61440 bytes

template <int K>
__global__ void __launch_bounds__(256, 2) gemm_mma(
    const __half* __restrict__ A, const __half* __restrict__ B,
    const float* __restrict__ bias, float* __restrict__ Cout,
    __half* __restrict__ Oh, const float* __restrict__ Rsrc,
    int N, int mode, int shift) {
    extern __shared__ __half smem[];
    uint32_t sb = smem_u32(smem);

    int tid = threadIdx.x, lane = tid & 31, wid = tid >> 5;
    int wm = wid >> 2, wn = wid & 3;       // 2 x 4 warp grid, 64x32 warp tiles
    int m0 = blockIdx.y * 128, n0 = blockIdx.x * 128;

    float acc[4][4][4];
    #pragma unroll
    for (int i = 0; i < 4; i++)
        #pragma unroll
        for (int j = 0; j < 4; j++)
            #pragma unroll
            for (int cjj = 0; cjj < 4; cjj++) acc[i][j][cjj] = 0.f;

    int rowA = lane & 15, colA = (lane >> 4) * 8;
    int rowB = (lane & 7) + ((lane >> 4) & 1) * 8;
    int colB = ((lane >> 3) & 1) * 8;

    int ldrow = tid >> 1;
    int ldseg = (tid & 1) * 2;
    constexpr int nch = K >> 5;

    // prologue: chunks 0,1 into stages 0,1
    #pragma unroll
    for (int p = 0; p < 2; ++p) {
        int k0 = p << 5;
        size_t ga = (size_t)(m0 + ldrow) * K + k0 + ldseg * 8;
        size_t gb = (size_t)(n0 + ldrow) * K + k0 + ldseg * 8;
        uint32_t s0 = sb + (uint32_t)p * STAGE_EL * 2 + (uint32_t)(ldrow * SPAD + ldseg * 8) * 2;
        cp16(s0 + OFF_A * 2, &A[ga]);      cp16(s0 + OFF_A * 2 + 16, &A[ga + 8]);
        cp16(s0 + OFF_B * 2, &B[gb]);      cp16(s0 + OFF_B * 2 + 16, &B[gb + 8]);
        CP_COMMIT();
    }

    #pragma unroll 8
    for (int ch = 0; ch < nch; ++ch) {
        int st_c = ch % 3;
        int st_i = (ch + 2) % 3;
        if (ch + 2 < nch) {
            int k0 = (ch + 2) << 5;
            size_t ga = (size_t)(m0 + ldrow) * K + k0 + ldseg * 8;
            size_t gb = (size_t)(n0 + ldrow) * K + k0 + ldseg * 8;
            uint32_t s0 = sb + (uint32_t)st_i * STAGE_EL * 2 + (uint32_t)(ldrow * SPAD + ldseg * 8) * 2;
            cp16(s0 + OFF_A * 2, &A[ga]);  cp16(s0 + OFF_A * 2 + 16, &A[ga + 8]);
            cp16(s0 + OFF_B * 2, &B[gb]);  cp16(s0 + OFF_B * 2 + 16, &B[gb + 8]);
        }
        CP_COMMIT();           // empty group when nothing issued keeps count uniform
        CP_WAIT(2);            // chunk ch's group complete
        __syncthreads();

        uint32_t stg = sb + (uint32_t)st_c * STAGE_EL * 2;
        uint32_t baseA = stg + OFF_A * 2;
        uint32_t baseB = stg + OFF_B * 2;

        #pragma unroll
        for (int ks = 0; ks < 2; ++ks) {
            uint32_t af[4][4], bf[2][4];
            #pragma unroll
            for (int am = 0; am < 4; ++am) {
                uint32_t ad = baseA + 2 * ((wm * 64 + am * 16 + rowA) * SPAD + ks * 16 + colA);
                LDSM_X4(af[am][0], af[am][1], af[am][2], af[am][3], ad);
            }
            #pragma unroll
            for (int bn = 0; bn < 2; ++bn) {
                uint32_t off = 2 * ((wn * 32 + bn * 16 + rowB) * SPAD + ks * 16 + colB);
                LDSM_X4(bf[bn][0], bf[bn][1], bf[bn][2], bf[bn][3], baseB + off);
            }
            #pragma unroll
            for (int am = 0; am < 4; ++am)
                #pragma unroll
                for (int an = 0; an < 4; ++an) {
                    int bn = an >> 1, p = (an & 1) * 2;
                    MMA16816(acc[am][an], af[am], bf[bn][p], bf[bn][p + 1]);
                }
        }
        __syncthreads();
    }

    int rbase = (lane >> 2);
    int cbase = (lane & 3) * 2;
    #pragma unroll
    for (int am = 0; am < 4; ++am) {
        #pragma unroll
        for (int h = 0; h < 2; ++h) {
            int m = m0 + wm * 64 + am * 16 + rbase + h * 8;
            int dst = m;
            if (mode == 3) {
                int win = m >> 6, n = m & 63;
                int bb = win >> 6, w = win & 63;
                int wh = w >> 3, ww = w & 7, th = n >> 3, tw = n & 7;
                int pr = (wh * 8 + th + shift) & 63;
                int pc = (ww * 8 + tw + shift) & 63;
                dst = (bb << 12) + (pr << 6) + pc;
            }
            #pragma unroll
            for (int an = 0; an < 4; ++an) {
                int col = n0 + wn * 32 + an * 8 + cbase;
                float v0 = acc[am][an][h * 2 + 0] + bias[col + 0];
                float v1 = acc[am][an][h * 2 + 1] + bias[col + 1];
                size_t oi = (size_t)dst * N + col;
                if (mode == 0) {
                    *reinterpret_cast<float2*>(&Cout[(size_t)m * N + col]) = make_float2(v0, v1);
                } else if (mode == 5) {
                    *reinterpret_cast<__half2*>(&Oh[(size_t)m * N + col]) = __floats2half2_rn(v0, v1);
                } else if (mode == 4) {
                    v0 = 0.5f * v0 * (1.0f + erff(v0 * 0.70710678118654752f));
                    v1 = 0.5f * v1 * (1.0f + erff(v1 * 0.70710678118654752f));
                    *reinterpret_cast<__half2*>(&Oh[(size_t)m * N + col]) = __floats2half2_rn(v0, v1);
                } else {  // 2 or 3: residual accumulate from Rsrc (each element once)
                    float2 old = *reinterpret_cast<const float2*>(&Rsrc[oi]);
                    old.x += v0;
                    old.y += v1;
                    *reinterpret_cast<float2*>(&Cout[oi]) = old;
                }
            }
        }
    }
}

// ======================= attention: conflict-free interleaved m, q in regs =====
__global__ void __launch_bounds__(256) attn_kernel(
    const __half* __restrict__ qkv, const float* __restrict__ rpb,
    __half* __restrict__ oh, int shift) {
    int bid = blockIdx.x;
    int win = bid >> 3, head = bid & 7;
    int tid = threadIdx.x;

    __shared__ float q[64][36];
    __shared__ float k[64][36];
    __shared__ float v[64][36];

    const float scale = 0.17677669529663687f;
    #pragma unroll
    for (int it = 0; it < 2; ++it) {
        int e = tid + it * 256;
        int n = e >> 3, dq = e & 7;
        size_t base = (size_t)(win * 64 + n) * (3 * C) + head * DHEAD + dq * 4;
        uint2 rq = *reinterpret_cast<const uint2*>(&qkv[base]);
        uint2 rk = *reinterpret_cast<const uint2*>(&qkv[base + C]);
        uint2 rv = *reinterpret_cast<const uint2*>(&qkv[base + 2 * C]);
        float2 q0 = __half22float2(*reinterpret_cast<__half2*>(&rq.x));
        float2 q1 = __half22float2(*reinterpret_cast<__half2*>(&rq.y));
        float2 k0 = __half22float2(*reinterpret_cast<__half2*>(&rk.x));
        float2 k1 = __half22float2(*reinterpret_cast<__half2*>(&rk.y));
        float2 vv0 = __half22float2(*reinterpret_cast<__half2*>(&rv.x));
        float2 vv1 = __half22float2(*reinterpret_cast<__half2*>(&rv.y));
        *reinterpret_cast<float4*>(&q[n][dq * 4]) =
            make_float4(q0.x * scale, q0.y * scale, q1.x * scale, q1.y * scale);
        *reinterpret_cast<float4*>(&k[n][dq * 4]) = make_float4(k0.x, k0.y, k1.x, k1.y);
        *reinterpret_cast<float4*>(&v[n][dq * 4]) = make_float4(vv0.x, vv0.y, vv1.x, vv1.y);
    }
    __syncthreads();

    int n = tid >> 2;
    int sub = tid & 3;
    int th_n = n >> 3, tw_n = n & 7;
    int w = win & 63;
    int wh = w >> 3, ww = w & 7;
    int lab_n = 0;
    if (shift) {
        int r = wh * 8 + th_n, c = ww * 8 + tw_n;
        int lr = (r < 56) ? 0 : ((r < 60) ? 1 : 2);
        int lc = (c < 56) ? 0 : ((c < 60) ? 1 : 2);
        lab_n = lr * 3 + lc;
    }

    // hoist q row into registers (loop-invariant)
    float4 qr[8];
    #pragma unroll
    for (int kq = 0; kq < 8; ++kq) qr[kq] = *reinterpret_cast<const float4*>(&q[n][kq * 4]);

    // interleaved m: quad lanes read ADJACENT rows (bank offset +4) -> conflict-free
    float att[16];
    #pragma unroll
    for (int mm = 0; mm < 16; ++mm) {
        int m = (mm << 2) | sub;
        float dot = 0.f;
        #pragma unroll
        for (int kq = 0; kq < 8; ++kq) {
            float4 kv = *reinterpret_cast<const float4*>(&k[m][kq * 4]);
            dot += qr[kq].x * kv.x + qr[kq].y * kv.y + qr[kq].z * kv.z + qr[kq].w * kv.w;
        }
        int th_m = m >> 3, tw_m = m & 7;
        int idx = (th_n - th_m + 7) * 15 + (tw_n - tw_m + 7);
        dot += rpb[idx * HEADS + head];
        if (shift) {
            int r = wh * 8 + th_m, c = ww * 8 + tw_m;
            int lr = (r < 56) ? 0 : ((r < 60) ? 1 : 2);
            int lc = (c < 56) ? 0 : ((c < 60) ? 1 : 2);
            if (lr * 3 + lc != lab_n) dot += -100.0f;
        }
        att[mm] = dot;
    }

    float mx = att[0];
    #pragma unroll
    for (int mm = 1; mm < 16; ++mm) mx = fmaxf(mx, att[mm]);
    mx = fmaxf(mx, __shfl_xor_sync(0xFFFFFFFFu, mx, 1));
    mx = fmaxf(mx, __shfl_xor_sync(0xFFFFFFFFu, mx, 2));
    float sum = 0.f;
    #pragma unroll
    for (int mm = 0; mm < 16; ++mm) {
        att[mm] = __expf(att[mm] - mx);
        sum += att[mm];
    }
    sum += __shfl_xor_sync(0xFFFFFFFFu, sum, 1);
    sum += __shfl_xor_sync(0xFFFFFFFFu, sum, 2);
    float inv = 1.0f / sum;
    #pragma unroll
    for (int mm = 0; mm < 16; ++mm) att[mm] *= inv;

    float4 part[8];
    #pragma unroll
    for (int dq = 0; dq < 8; ++dq) part[dq] = make_float4(0.f, 0.f, 0.f, 0.f);
    #pragma unroll
    for (int mm = 0; mm < 16; ++mm) {
        int m = (mm << 2) | sub;
        float a = att[mm];
        #pragma unroll
        for (int dq = 0; dq < 8; ++dq) {
            float4 vv = *reinterpret_cast<const float4*>(&v[m][dq * 4]);
            part[dq].x += a * vv.x;
            part[dq].y += a * vv.y;
            part[dq].z += a * vv.z;
            part[dq].w += a * vv.w;
        }
    }
    #pragma unroll
    for (int dq = 0; dq < 8; ++dq) {
        #pragma unroll
        for (int o = 1; o <= 2; o <<= 1) {
            part[dq].x += __shfl_xor_sync(0xFFFFFFFFu, part[dq].x, o);
            part[dq].y += __shfl_xor_sync(0xFFFFFFFFu, part[dq].y, o);
            part[dq].z += __shfl_xor_sync(0xFFFFFFFFu, part[dq].z, o);
            part[dq].w += __shfl_xor_sync(0xFFFFFFFFu, part[dq].w, o);
        }
    }
    {
        float o8[8] = { part[sub * 2].x, part[sub * 2].y, part[sub * 2].z, part[sub * 2].w,
                        part[sub * 2 + 1].x, part[sub * 2 + 1].y, part[sub * 2 + 1].z, part[sub * 2 + 1].w };
        __half hh[8];
        #pragma unroll
        for (int j = 0; j < 8; ++j) hh[j] = __float2half_rn(o8[j]);
        size_t oi = (size_t)(win * 64 + n) * C + head * DHEAD + sub * 8;
        *reinterpret_cast<uint4*>(&oh[oi]) = *reinterpret_cast<uint4*>(hh);
    }
}

// ======================= launch =======================
extern "C" void kernel_launch(void* const* d_in, const int* in_sizes, int n_in,
                              void* d_out, int out_size) {
    const float* x      = (const float*)d_in[0];
    const float* qkv_w  = (const float*)d_in[1];
    const float* qkv_b  = (const float*)d_in[2];
    const float* proj_w = (const float*)d_in[3];
    const float* proj_b = (const float*)d_in[4];
    const float* ln1_g  = (const float*)d_in[5];
    const float* ln1_b  = (const float*)d_in[6];
    const float* ln2_g  = (const float*)d_in[7];
    const float* ln2_b  = (const float*)d_in[8];
    const float* fc1_w  = (const float*)d_in[9];
    const float* fc1_b  = (const float*)d_in[10];
    const float* fc2_w  = (const float*)d_in[11];
    const float* fc2_b  = (const float*)d_in[12];
    const float* rpb    = (const float*)d_in[13];
    float* state = (float*)d_out;

    __half *a, *qkv, *ao, *l2, *f1, *wq, *wp, *w1, *w2;
    cudaGetSymbolAddress((void**)&a, g_a);
    cudaGetSymbolAddress((void**)&qkv, g_qkv);
    cudaGetSymbolAddress((void**)&ao, g_ao);
    cudaGetSymbolAddress((void**)&l2, g_l2);
    cudaGetSymbolAddress((void**)&f1, g_f1);
    cudaGetSymbolAddress((void**)&wq, g_wq);
    cudaGetSymbolAddress((void**)&wp, g_wp);
    cudaGetSymbolAddress((void**)&w1, g_w1);
    cudaGetSymbolAddress((void**)&w2, g_w2);

    cudaFuncSetAttribute(gemm_mma<256>, cudaFuncAttributeMaxDynamicSharedMemorySize, GEMM_SMEM);
    cudaFuncSetAttribute(gemm_mma<1024>, cudaFuncAttributeMaxDynamicSharedMemorySize, GEMM_SMEM);

    dim3 tb(32, 32);
    // just-in-time wconv ordering: gemm_qkv lands at launch index 2, attn at 3
    wconv_kernel<<<dim3(256 / 32, 768 / 32, DEPTH), tb>>>(qkv_w, wq, 256, 768);       // 0

    for (int i = 0; i < DEPTH; ++i) {
        int shift = (i % 2 == 0) ? 0 : (WS / 2);
        size_t wq0 = (size_t)i * 768 * 256;
        size_t wp0 = (size_t)i * 256 * 256;
        size_t w10 = (size_t)i * 1024 * 256;
        size_t w20 = (size_t)i * 256 * 1024;
        const float* resid = (i == 0) ? x : state;   // residual stream source

        // LN1 + shift + window partition
        ln_kernel<<<TOK / 8, 256>>>(resid, ln1_g + i * C, ln1_b + i * C, a, shift, 1);    // 1
        // qkv -> fp16
        gemm_mma<256><<<dim3(768 / 128, TOK / 128), 256, GEMM_SMEM>>>(
            a, wq + wq0, qkv_b + (size_t)i * 768, nullptr, qkv, nullptr, 768, 5, 0);      // 2
        attn_kernel<<<NWIN * HEADS, 256>>>(qkv, rpb + (size_t)i * 225 * HEADS, ao, shift);// 3
        if (i == 0)
            wconv_kernel<<<dim3(256 / 32, 256 / 32, DEPTH), tb>>>(proj_w, wp, 256, 256);  // 4
        // proj + window reverse + unshift + residual
        gemm_mma<256><<<dim3(256 / 128, TOK / 128), 256, GEMM_SMEM>>>(
            ao, wp + wp0, proj_b + (size_t)i * 256, state, nullptr, resid, 256, 3, shift);
        if (i == 0)
            wconv_kernel<<<dim3(256 / 32, 1024 / 32, DEPTH), tb>>>(fc1_w, w1, 256, 1024);
        ln_kernel<<<TOK / 8, 256>>>(state, ln2_g + i * C, ln2_b + i * C, l2, 0, 0);
        gemm_mma<256><<<dim3(HIDDEN / 128, TOK / 128), 256, GEMM_SMEM>>>(
            l2, w1 + w10, fc1_b + (size_t)i * HIDDEN, nullptr, f1, nullptr, HIDDEN, 4, 0);
        if (i == 0)
            wconv_kernel<<<dim3(1024 / 32, 256 / 32, DEPTH), tb>>>(fc2_w, w2, 1024, 256);
        gemm_mma<1024><<<dim3(256 / 128, TOK / 128), 256, GEMM_SMEM>>>(
            f1, w2 + w20, fc2_b + (size_t)i * 256, state, nullptr, state, 256, 2, 0);
    }
}